// round 4
// baseline (speedup 1.0000x reference)
#include <cuda_runtime.h>
#include <math.h>

#define BATCHES 8
#define NMAX    128
#define PE      64
#define NE      5
#define DS      64
#define NF      8
#define TOTAL   (BATCHES*NMAX)       // 1024
#define PROJC   (4*NE*PE)            // 1280
#define ZCOUNT  (BATCHES*NE*NMAX*NMAX)

#define OFF_EHAT 0
#define OFF_XHAT (BATCHES*NMAX*NMAX*NE)            // 655360
#define OFF_EDGE (OFF_XHAT + TOTAL*NF)             // 663552
#define OFF_MASK (OFF_EDGE + BATCHES*NMAX*NMAX)    // 794624

__device__ float  g_proj[TOTAL*PROJC];
__device__ float  g_z[ZCOUNT];
__device__ float  g_a[BATCHES*NE*NMAX];
__device__ float  g_r[BATCHES*NMAX];
__device__ int    g_node[BATCHES*NMAX];
__device__ int    g_mask[BATCHES*NMAX];
__device__ int    g_cnt[BATCHES];
__device__ float  g_coef[BATCHES];
__device__ float  g_u[DS];
__device__ float  g_v[DS];
__device__ float  g_sc[4];           // H1, HW0, HWU, HWV (all pre-halved)

#define FMA2(d,a,b,c) asm("fma.rn.f32x2 %0, %1, %2, %3;" : "=l"(d) : "l"(a), "l"(b), "l"(c))
#define MUL2(d,a,b)   asm("mul.rn.f32x2 %0, %1, %2;" : "=l"(d) : "l"(a), "l"(b))
#define PACK2(d,lo,hi) asm("mov.b64 %0, {%1, %2};" : "=l"(d) : "r"(__float_as_uint(lo)), "r"(__float_as_uint(hi)))

__device__ __forceinline__ unsigned long long dup2(float v) {
    unsigned long long d; PACK2(d, v, v); return d;
}
__device__ __forceinline__ float lo2(unsigned long long v) { return __uint_as_float((unsigned int)v); }
__device__ __forceinline__ float hi2(unsigned long long v) { return __uint_as_float((unsigned int)(v >> 32)); }

// Taylor coefficients of erf(x/sqrt(2)) = x * sum c_k x^(2k), valid |x|<=1.5 (err<4.5e-6)
#define C0  0.7978845608028654f
#define C1 (-0.13298076013381092f)
#define C2  0.019947114020071635f
#define C3 (-0.0023746564309608790f)
#define C4  2.3087512708529163e-4f
#define C5 (-1.8888357703977833e-5f)
#define C6  1.3319387846161196e-6f
#define C7 (-8.2452514340561257e-8f)

// ---------------------------------------------------------------------------
// K0: dense map, counts, coef, u/v, hoisted scalars, mask output.
// ---------------------------------------------------------------------------
__global__ void k_setup(const int* __restrict__ batch, const float* __restrict__ q,
                        const float* __restrict__ w_phi, const float* __restrict__ b_phi,
                        const float* __restrict__ w_ctx,
                        const float* __restrict__ w_self, const float* __restrict__ b_self,
                        const float* __restrict__ w_out,
                        float* __restrict__ out_mask) {
    __shared__ int s_start[BATCHES];
    __shared__ int s_cnt[BATCHES];
    __shared__ float s_red[4][64];
    int t = threadIdx.x;                // 0..1023, one block
    if (t < BATCHES) { s_cnt[t] = 0; s_start[t] = 0; }
    g_node[t] = -1;
    g_mask[t] = 0;
    out_mask[t] = 0.0f;
    __syncthreads();
    int b = batch[t];
    if (t == 0 || batch[t-1] != b) s_start[b] = t;
    atomicAdd(&s_cnt[b], 1);
    if (t < DS) {
        float u = 0.f, v = 0.f;
        #pragma unroll 8
        for (int k = 0; k < DS; k++) {
            float wc = w_ctx[k*DS + t];
            u = fmaf(w_phi[k], wc, u);
            v = fmaf(b_phi[k], wc, v);
        }
        g_u[t] = u; g_v[t] = v;
        float wo = w_out[t];
        s_red[0][t] = wo * w_self[t];
        s_red[1][t] = wo * b_self[t];
        s_red[2][t] = wo * u;
        s_red[3][t] = wo * v;
    }
    __syncthreads();
    int pos = t - s_start[b];
    int di = b*NMAX + pos;
    g_node[di] = t;
    g_mask[di] = 1;
    out_mask[di] = 1.0f;
    if (t < BATCHES) {
        g_cnt[t] = s_cnt[t];
        float qq = q[t];
        float c = cosf(6.283185307179586f*qq);
        float s = sinf(6.283185307179586f*qq);
        g_coef[t] = (2.0f - c) / s;
    }
    if (t < 32) {
        #pragma unroll
        for (int j = 0; j < 4; j++) {
            float sv = s_red[j][t] + s_red[j][t+32];
            #pragma unroll
            for (int off = 16; off > 0; off >>= 1)
                sv += __shfl_xor_sync(0xffffffffu, sv, off);
            if (t == 0) g_sc[j] = 0.5f * sv;
        }
    }
}

// ---------------------------------------------------------------------------
// K1: proj = x @ w_attn + b_attn (dense layout, packed f32x2)
//     AND x_hat (blockIdx.x == 20).
// ---------------------------------------------------------------------------
__global__ void k_projx(const float* __restrict__ x, const float* __restrict__ w,
                        const float* __restrict__ bias,
                        const float* __restrict__ w_node, const float* __restrict__ b_node,
                        float* __restrict__ out_xhat) {
    if (blockIdx.x == 20) {
        int base = blockIdx.y * 512;
        #pragma unroll
        for (int l = 0; l < 2; l++) {
            int id = base + threadIdx.x + l*256;
            int node = id / NF, f = id % NF;
            float acc = 0.f;
            #pragma unroll 8
            for (int k = 0; k < PE; k++)
                acc = fmaf(__ldg(&x[node*PE + k]), __ldg(&w_node[k*NF + f]), acc);
            out_xhat[id] = acc + b_node[f];
        }
        return;
    }
    __shared__ unsigned long long Ad[64][64];   // duplicated A, [row][k]   32KB
    __shared__ unsigned long long Wp[64][32];   // col-paired W, [k][pair]  16KB
    int tid = threadIdx.x;              // 256 threads
    int tx = tid & 15, ty = tid >> 4;   // 16x16
    int row0 = blockIdx.y * 64;
    int col0 = blockIdx.x * 64;
    #pragma unroll
    for (int l = 0; l < 4; l++) {
        int e = tid + l*256;            // 0..1023 (r, kq)
        int r = e >> 4, kq = (e & 15) * 4;
        int node = g_node[row0 + r];
        float4 v = make_float4(0.f,0.f,0.f,0.f);
        if (node >= 0) v = *(const float4*)&x[node*PE + kq];
        Ad[r][kq+0] = dup2(v.x);
        Ad[r][kq+1] = dup2(v.y);
        Ad[r][kq+2] = dup2(v.z);
        Ad[r][kq+3] = dup2(v.w);
    }
    #pragma unroll
    for (int l = 0; l < 4; l++) {
        int e = tid + l*256;            // (k, cq)
        int k = e >> 4, cq = (e & 15) * 4;
        float4 v = *(const float4*)&w[k*PROJC + col0 + cq];
        unsigned long long p0, p1;
        PACK2(p0, v.x, v.y);
        PACK2(p1, v.z, v.w);
        Wp[k][cq/2]   = p0;
        Wp[k][cq/2+1] = p1;
    }
    __syncthreads();
    unsigned long long acc[4][2];
    #pragma unroll
    for (int i = 0; i < 4; i++) { acc[i][0] = 0ull; acc[i][1] = 0ull; }
    #pragma unroll 4
    for (int kk = 0; kk < 64; kk += 2) {
        ulonglong2 ai[4];
        #pragma unroll
        for (int i = 0; i < 4; i++)
            ai[i] = *(const ulonglong2*)&Ad[ty + 16*i][kk];
        unsigned long long b00 = Wp[kk][tx],   b10 = Wp[kk][tx+16];
        unsigned long long b01 = Wp[kk+1][tx], b11 = Wp[kk+1][tx+16];
        #pragma unroll
        for (int i = 0; i < 4; i++) {
            FMA2(acc[i][0], ai[i].x, b00, acc[i][0]);
            FMA2(acc[i][0], ai[i].y, b01, acc[i][0]);
            FMA2(acc[i][1], ai[i].x, b10, acc[i][1]);
            FMA2(acc[i][1], ai[i].y, b11, acc[i][1]);
        }
    }
    #pragma unroll
    for (int i = 0; i < 4; i++) {
        int r = row0 + ty + 16*i;
        int node = g_node[r];
        #pragma unroll
        for (int j = 0; j < 2; j++) {
            int cp = tx + 16*j;
            int c = col0 + 2*cp;
            float v0 = 0.f, v1 = 0.f;
            if (node >= 0) {
                v0 = lo2(acc[i][j]) + bias[c];
                v1 = hi2(acc[i][j]) + bias[c+1];
            }
            *(float2*)&g_proj[r*PROJC + c] = make_float2(v0, v1);
        }
    }
}

// ---------------------------------------------------------------------------
// K2: fused z GEMM (packed f32x2) + masked row means.
// ---------------------------------------------------------------------------
__global__ void k_zrows() {
    __shared__ unsigned long long Kd[64][17];   // duplicated K values [k][row]
    __shared__ float Qt[64][130];               // transposed Q [k][m]
    __shared__ float s_maskf[NMAX];
    const float scale = 0.05590169943749474f;   // 1/sqrt(320)
    int tid = threadIdx.x;
    int tx = tid & 31, wy = tid >> 5;           // 32 lanes x 4 warps
    int tile = blockIdx.x, e = blockIdx.y, b = blockIdx.z;
    int row0 = tile * 16;
    int base_row = b * NMAX;
    float coef = g_coef[b];
    if (tid < NMAX) s_maskf[tid] = (float)g_mask[base_row + tid];

    unsigned long long acc[4][2];
    #pragma unroll
    for (int i = 0; i < 4; i++) { acc[i][0] = 0ull; acc[i][1] = 0ull; }

    #pragma unroll
    for (int p = 0; p < 2; p++) {
        float cs = p ? coef : 1.0f;
        int koff = (p ? 2*NE*PE : 0) + e*PE;
        int qoff = (p ? 3*NE*PE : NE*PE) + e*PE;
        if (p) __syncthreads();
        #pragma unroll
        for (int l = 0; l < 2; l++) {
            int e4 = tid + l*128;
            int r = e4 >> 4;
            int kq = (e4 & 15) * 4;
            float4 v = *(const float4*)&g_proj[(base_row + row0 + r)*PROJC + koff + kq];
            Kd[kq+0][r] = dup2(v.x * cs);
            Kd[kq+1][r] = dup2(v.y * cs);
            Kd[kq+2][r] = dup2(v.z * cs);
            Kd[kq+3][r] = dup2(v.w * cs);
        }
        #pragma unroll
        for (int l = 0; l < 16; l++) {
            int e4 = tid + l*128;
            int r = e4 >> 4;
            int kq = (e4 & 15) * 4;
            float4 v = *(const float4*)&g_proj[(base_row + r)*PROJC + qoff + kq];
            Qt[kq+0][r] = v.x;
            Qt[kq+1][r] = v.y;
            Qt[kq+2][r] = v.z;
            Qt[kq+3][r] = v.w;
        }
        __syncthreads();
        #pragma unroll 4
        for (int k = 0; k < 64; k++) {
            unsigned long long b0 = *(const unsigned long long*)&Qt[k][2*tx];
            unsigned long long b1 = *(const unsigned long long*)&Qt[k][64 + 2*tx];
            #pragma unroll
            for (int i = 0; i < 4; i++) {
                unsigned long long aa = Kd[k][wy*4 + i];
                FMA2(acc[i][0], aa, b0, acc[i][0]);
                FMA2(acc[i][1], aa, b1, acc[i][1]);
            }
        }
    }

    int cnt = g_cnt[b];
    #pragma unroll
    for (int i = 0; i < 4; i++) {
        int n = row0 + wy*4 + i;
        float z0 = lo2(acc[i][0]) * scale;
        float z1 = hi2(acc[i][0]) * scale;
        float z2 = lo2(acc[i][1]) * scale;
        float z3 = hi2(acc[i][1]) * scale;
        long zb = (long)((b*NE + e)*NMAX + n) * NMAX;
        int m0 = 2*tx, m2 = 64 + 2*tx;
        *(float2*)&g_z[zb + m0] = make_float2(z0, z1);
        *(float2*)&g_z[zb + m2] = make_float2(z2, z3);
        float s = z0 * (s_maskf[m0]   * (float)(m0   != n))
                + z1 * (s_maskf[m0+1] * (float)(m0+1 != n))
                + z2 * (s_maskf[m2]   * (float)(m2   != n))
                + z3 * (s_maskf[m2+1] * (float)(m2+1 != n));
        #pragma unroll
        for (int off = 16; off > 0; off >>= 1)
            s += __shfl_xor_sync(0xffffffffu, s, off);
        if (tx == 0) {
            int mn = g_mask[base_row + n];
            float cm1 = (float)(cnt - 1);
            float denom = fmaxf(cm1, 1.0f);
            g_a[(b*NE + e)*NMAX + n] = mn ? (s / denom) : 0.0f;
            if (e == 0) g_r[base_row + n] = mn ? (cm1 / denom) : 0.0f;
        }
    }
}

// ---------------------------------------------------------------------------
// K3: packed-polynomial gelu sum + edge_mask.
// Block = (ngroup of 4 n, e, b), 256 threads: t = nl*64 + mp; m = 2mp, 2mp+1.
// acc = sum_d wo2[d] * xx * erf(xx/sqrt2)  (poly in t=xx^2, f32x2 packed)
// e = acc + zv*H1 + S0[nl] + b_out
// ---------------------------------------------------------------------------
__global__ void k_main(const float* __restrict__ w_self, const float* __restrict__ b_self,
                       const float* __restrict__ w_out, const float* __restrict__ b_out,
                       float* __restrict__ out_e, float* __restrict__ out_edge) {
    __shared__ ulonglong2 s_A[4][DS];           // {ws_dup, base_dup}
    __shared__ unsigned long long s_W[DS];      // wo2_dup
    __shared__ float s_S0[4];
    int t = threadIdx.x;
    int ng = blockIdx.x, e = blockIdx.y, b = blockIdx.z;
    int mp = t & 63, nl = t >> 6;
    int n = ng*4 + nl;
    {   // fill stage: one (nl, d) per thread
        int d = t & 63, fl = t >> 6;
        int nn = ng*4 + fl;
        float a = g_a[(b*NE + e)*NMAX + nn];
        float r = g_r[b*NMAX + nn];
        float base = fmaf(a, g_u[d], fmaf(r, g_v[d], b_self[d]));
        s_A[fl][d] = make_ulonglong2(dup2(w_self[d]), dup2(base));
        if (d == 0)
            s_S0[fl] = fmaf(a, g_sc[2], fmaf(r, g_sc[3], g_sc[1]));
        if (t < DS) s_W[t] = dup2(0.5f * w_out[t]);
    }
    __syncthreads();

    const unsigned long long k0 = dup2(C0), k1 = dup2(C1), k2 = dup2(C2), k3 = dup2(C3);
    const unsigned long long k4 = dup2(C4), k5 = dup2(C5), k6 = dup2(C6), k7 = dup2(C7);

    long zb = (long)((b*NE + e)*NMAX + n) * NMAX;
    float2 z2 = *(const float2*)&g_z[zb + 2*mp];
    unsigned long long zv2; PACK2(zv2, z2.x, z2.y);

    unsigned long long acc = 0ull;
    float tmax = 0.0f;
    #pragma unroll 8
    for (int d = 0; d < DS; d++) {
        ulonglong2 ab = s_A[nl][d];
        unsigned long long xx, tt, p, q;
        FMA2(xx, zv2, ab.x, ab.y);
        MUL2(tt, xx, xx);
        p = k7;
        FMA2(p, p, tt, k6);
        FMA2(p, p, tt, k5);
        FMA2(p, p, tt, k4);
        FMA2(p, p, tt, k3);
        FMA2(p, p, tt, k2);
        FMA2(p, p, tt, k1);
        FMA2(p, p, tt, k0);
        MUL2(q, tt, p);
        FMA2(acc, s_W[d], q, acc);
        tmax = fmaxf(tmax, lo2(tt));
        tmax = fmaxf(tmax, hi2(tt));
    }
    if (tmax > 2.25f) {                 // rare exact fallback (|xx| > 1.5 seen)
        float al = 0.f, ah = 0.f;
        for (int d = 0; d < DS; d++) {
            ulonglong2 ab = s_A[nl][d];
            float ws = lo2(ab.x), base = lo2(ab.y), w2 = lo2(s_W[d]);
            float xl = fmaf(z2.x, ws, base);
            float xh = fmaf(z2.y, ws, base);
            al = fmaf(w2, xl * erff(xl * 0.7071067811865476f), al);
            ah = fmaf(w2, xh * erff(xh * 0.7071067811865476f), ah);
        }
        PACK2(acc, al, ah);
    }
    float h1 = g_sc[0];
    float cst = s_S0[nl] + b_out[0];
    float e0 = fmaf(z2.x, h1, lo2(acc)) + cst;
    float e1 = fmaf(z2.y, h1, hi2(acc)) + cst;
    int m = 2*mp;
    out_e[((long)(b*NMAX + m  )*NMAX + n)*NE + e] = e0;
    out_e[((long)(b*NMAX + m+1)*NMAX + n)*NE + e] = e1;
    if (e == 0) {
        int mn = g_mask[b*NMAX + n];
        float v0 = (float)(mn & g_mask[b*NMAX + m]   & (int)(n != m));
        float v1 = (float)(mn & g_mask[b*NMAX + m+1] & (int)(n != m+1));
        *(float2*)&out_edge[(b*NMAX + n)*NMAX + m] = make_float2(v0, v1);
    }
}

extern "C" void kernel_launch(void* const* d_in, const int* in_sizes, int n_in,
                              void* d_out, int out_size) {
    const float* x      = (const float*)d_in[0];
    const int*   batch  = (const int*)  d_in[1];
    const float* q      = (const float*)d_in[2];
    const float* w_attn = (const float*)d_in[3];
    const float* b_attn = (const float*)d_in[4];
    const float* w_node = (const float*)d_in[5];
    const float* b_node = (const float*)d_in[6];
    const float* w_phi  = (const float*)d_in[7];
    const float* b_phi  = (const float*)d_in[8];
    const float* w_ctx  = (const float*)d_in[9];
    const float* w_self = (const float*)d_in[10];
    const float* b_self = (const float*)d_in[11];
    const float* w_out  = (const float*)d_in[12];
    const float* b_out  = (const float*)d_in[13];
    float* out = (float*)d_out;

    k_setup<<<1, 1024>>>(batch, q, w_phi, b_phi, w_ctx, w_self, b_self, w_out, out + OFF_MASK);
    k_projx<<<dim3(21, 16), 256>>>(x, w_attn, b_attn, w_node, b_node, out + OFF_XHAT);
    k_zrows<<<dim3(8, NE, BATCHES), 128>>>();
    k_main<<<dim3(32, NE, BATCHES), 256>>>(w_self, b_self, w_out, b_out,
                                           out + OFF_EHAT, out + OFF_EDGE);
}

// round 5
// speedup vs baseline: 1.0012x; 1.0012x over previous
#include <cuda_runtime.h>
#include <math.h>

#define BATCHES 8
#define NMAX    128
#define PE      64
#define NE      5
#define DS      64
#define NF      8
#define TOTAL   (BATCHES*NMAX)
#define PROJC   (4*NE*PE)
#define ZCOUNT  (BATCHES*NE*NMAX*NMAX)

#define OFF_EHAT 0
#define OFF_XHAT (BATCHES*NMAX*NMAX*NE)
#define OFF_EDGE (OFF_XHAT + TOTAL*NF)
#define OFF_MASK (OFF_EDGE + BATCHES*NMAX*NMAX)

typedef unsigned long long ull;

__device__ float  g_proj[TOTAL*PROJC];
__device__ float  g_z[ZCOUNT];
__device__ float  g_a[BATCHES*NE*NMAX];
__device__ float  g_r[BATCHES*NMAX];
__device__ int    g_node[BATCHES*NMAX];
__device__ int    g_mask[BATCHES*NMAX];
__device__ int    g_cnt[BATCHES];
__device__ float  g_coef[BATCHES];
__device__ float  g_u[DS];
__device__ float  g_v[DS];
__device__ float  g_sc[4];

#define FMA2(d,a,b,c) asm("fma.rn.f32x2 %0, %1, %2, %3;" : "=l"(d) : "l"(a), "l"(b), "l"(c))
#define MUL2(d,a,b)   asm("mul.rn.f32x2 %0, %1, %2;" : "=l"(d) : "l"(a), "l"(b))
#define PACK2(d,lo,hi) asm("mov.b64 %0, {%1, %2};" : "=l"(d) : "r"(__float_as_uint(lo)), "r"(__float_as_uint(hi)))

__device__ __forceinline__ ull dup2(float v) { ull d; PACK2(d, v, v); return d; }
__device__ __forceinline__ float lo2(ull v) { return __uint_as_float((unsigned int)v); }
__device__ __forceinline__ float hi2(ull v) { return __uint_as_float((unsigned int)(v >> 32)); }

#define C0  0.7978845608028654f
#define C1 (-0.13298076013381092f)
#define C2  0.019947114020071635f
#define C3 (-0.0023746564309608790f)
#define C4  2.3087512708529163e-4f
#define C5 (-1.8888357703977833e-5f)

// ---------------------------------------------------------------------------
__global__ void k_setup(const int* __restrict__ batch, const float* __restrict__ q,
                        const float* __restrict__ w_phi, const float* __restrict__ b_phi,
                        const float* __restrict__ w_ctx,
                        const float* __restrict__ w_self, const float* __restrict__ b_self,
                        const float* __restrict__ w_out,
                        float* __restrict__ out_mask) {
    __shared__ int s_start[BATCHES];
    __shared__ int s_cnt[BATCHES];
    __shared__ float s_red[4][64];
    int t = threadIdx.x;
    if (t < BATCHES) { s_cnt[t] = 0; s_start[t] = 0; }
    g_node[t] = -1;
    g_mask[t] = 0;
    out_mask[t] = 0.0f;
    __syncthreads();
    int b = batch[t];
    if (t == 0 || batch[t-1] != b) s_start[b] = t;
    atomicAdd(&s_cnt[b], 1);
    if (t < DS) {
        float u = 0.f, v = 0.f;
        #pragma unroll 8
        for (int k = 0; k < DS; k++) {
            float wc = w_ctx[k*DS + t];
            u = fmaf(w_phi[k], wc, u);
            v = fmaf(b_phi[k], wc, v);
        }
        g_u[t] = u; g_v[t] = v;
        float wo = w_out[t];
        s_red[0][t] = wo * w_self[t];
        s_red[1][t] = wo * b_self[t];
        s_red[2][t] = wo * u;
        s_red[3][t] = wo * v;
    }
    __syncthreads();
    int pos = t - s_start[b];
    int di = b*NMAX + pos;
    g_node[di] = t;
    g_mask[di] = 1;
    out_mask[di] = 1.0f;
    if (t < BATCHES) {
        g_cnt[t] = s_cnt[t];
        float qq = q[t];
        float c = cosf(6.283185307179586f*qq);
        float s = sinf(6.283185307179586f*qq);
        g_coef[t] = (2.0f - c) / s;
    }
    if (t < 32) {
        #pragma unroll
        for (int j = 0; j < 4; j++) {
            float sv = s_red[j][t] + s_red[j][t+32];
            #pragma unroll
            for (int off = 16; off > 0; off >>= 1)
                sv += __shfl_xor_sync(0xffffffffu, sv, off);
            if (t == 0) g_sc[j] = 0.5f * sv;
        }
    }
}

// ---------------------------------------------------------------------------
__global__ void k_projx(const float* __restrict__ x, const float* __restrict__ w,
                        const float* __restrict__ bias,
                        const float* __restrict__ w_node, const float* __restrict__ b_node,
                        float* __restrict__ out_xhat) {
    if (blockIdx.x == 20) {
        int base = blockIdx.y * 512;
        #pragma unroll
        for (int l = 0; l < 2; l++) {
            int id = base + threadIdx.x + l*256;
            int node = id / NF, f = id % NF;
            float acc = 0.f;
            #pragma unroll 8
            for (int k = 0; k < PE; k++)
                acc = fmaf(__ldg(&x[node*PE + k]), __ldg(&w_node[k*NF + f]), acc);
            out_xhat[id] = acc + b_node[f];
        }
        return;
    }
    __shared__ ull Ad[64][64];
    __shared__ ull Wp[64][32];
    int tid = threadIdx.x;
    int tx = tid & 15, ty = tid >> 4;
    int row0 = blockIdx.y * 64;
    int col0 = blockIdx.x * 64;
    #pragma unroll
    for (int l = 0; l < 4; l++) {
        int e = tid + l*256;
        int r = e >> 4, kq = (e & 15) * 4;
        int node = g_node[row0 + r];
        float4 v = make_float4(0.f,0.f,0.f,0.f);
        if (node >= 0) v = *(const float4*)&x[node*PE + kq];
        Ad[r][kq+0] = dup2(v.x);
        Ad[r][kq+1] = dup2(v.y);
        Ad[r][kq+2] = dup2(v.z);
        Ad[r][kq+3] = dup2(v.w);
    }
    #pragma unroll
    for (int l = 0; l < 4; l++) {
        int e = tid + l*256;
        int k = e >> 4, cq = (e & 15) * 4;
        float4 v = *(const float4*)&w[k*PROJC + col0 + cq];
        ull p0, p1;
        PACK2(p0, v.x, v.y);
        PACK2(p1, v.z, v.w);
        Wp[k][cq/2]   = p0;
        Wp[k][cq/2+1] = p1;
    }
    __syncthreads();
    ull acc[4][2];
    #pragma unroll
    for (int i = 0; i < 4; i++) { acc[i][0] = 0ull; acc[i][1] = 0ull; }
    #pragma unroll 4
    for (int kk = 0; kk < 64; kk += 2) {
        ulonglong2 ai[4];
        #pragma unroll
        for (int i = 0; i < 4; i++)
            ai[i] = *(const ulonglong2*)&Ad[ty + 16*i][kk];
        ull b00 = Wp[kk][tx],   b10 = Wp[kk][tx+16];
        ull b01 = Wp[kk+1][tx], b11 = Wp[kk+1][tx+16];
        #pragma unroll
        for (int i = 0; i < 4; i++) {
            FMA2(acc[i][0], ai[i].x, b00, acc[i][0]);
            FMA2(acc[i][0], ai[i].y, b01, acc[i][0]);
            FMA2(acc[i][1], ai[i].x, b10, acc[i][1]);
            FMA2(acc[i][1], ai[i].y, b11, acc[i][1]);
        }
    }
    #pragma unroll
    for (int i = 0; i < 4; i++) {
        int r = row0 + ty + 16*i;
        int node = g_node[r];
        #pragma unroll
        for (int j = 0; j < 2; j++) {
            int cp = tx + 16*j;
            int c = col0 + 2*cp;
            float v0 = 0.f, v1 = 0.f;
            if (node >= 0) {
                v0 = lo2(acc[i][j]) + bias[c];
                v1 = hi2(acc[i][j]) + bias[c+1];
            }
            *(float2*)&g_proj[r*PROJC + c] = make_float2(v0, v1);
        }
    }
}

// ---------------------------------------------------------------------------
// K2: z GEMM (packed f32x2), XOR-swizzled conflict-free smem, fused row means.
// ---------------------------------------------------------------------------
__global__ void __launch_bounds__(128) k_zrows() {
    __shared__ ull Kd[64][17];
    __shared__ float Qt[64][130];
    __shared__ float s_maskf[NMAX];
    const float scale = 0.05590169943749474f;
    int tid = threadIdx.x;
    int tx = tid & 31, wy = tid >> 5;
    int tile = blockIdx.x, e = blockIdx.y, b = blockIdx.z;
    int row0 = tile * 16;
    int base_row = b * NMAX;
    float coef = g_coef[b];
    s_maskf[tid] = (float)g_mask[base_row + tid];

    ull acc[4][2];
    #pragma unroll
    for (int i = 0; i < 4; i++) { acc[i][0] = 0ull; acc[i][1] = 0ull; }

    #pragma unroll
    for (int p = 0; p < 2; p++) {
        float cs = p ? coef : 1.0f;
        int koff = (p ? 2*NE*PE : 0) + e*PE;
        int qoff = (p ? 3*NE*PE : NE*PE) + e*PE;
        if (p) __syncthreads();
        #pragma unroll
        for (int l = 0; l < 2; l++) {
            int e4 = tid + l*128;
            int r = e4 >> 4;
            int kq = (e4 & 15) * 4;
            int sw = (kq >> 4) & 3;
            float4 v = *(const float4*)&g_proj[(base_row + row0 + r)*PROJC + koff + kq];
            Kd[kq+0][r ^ sw] = dup2(v.x * cs);
            Kd[kq+1][r ^ sw] = dup2(v.y * cs);
            Kd[kq+2][r ^ sw] = dup2(v.z * cs);
            Kd[kq+3][r ^ sw] = dup2(v.w * cs);
        }
        #pragma unroll
        for (int l = 0; l < 16; l++) {
            int e4 = tid + l*128;
            int m = e4 >> 4;
            int kq = (e4 & 15) * 4;
            int ms = m ^ (((kq >> 4) & 3) << 1);
            float4 v = *(const float4*)&g_proj[(base_row + m)*PROJC + qoff + kq];
            Qt[kq+0][ms] = v.x;
            Qt[kq+1][ms] = v.y;
            Qt[kq+2][ms] = v.z;
            Qt[kq+3][ms] = v.w;
        }
        __syncthreads();
        #pragma unroll
        for (int kg = 0; kg < 4; kg++) {
            int c0 = (2*tx) ^ (kg << 1);
            int r0s = (4*wy + 0) ^ kg;
            int r1s = (4*wy + 1) ^ kg;
            int r2s = (4*wy + 2) ^ kg;
            int r3s = (4*wy + 3) ^ kg;
            #pragma unroll
            for (int kk = 0; kk < 16; kk++) {
                int k = kg*16 + kk;
                ull b0 = *(const ull*)&Qt[k][c0];
                ull b1 = *(const ull*)&Qt[k][c0 + 64];
                ull a0 = Kd[k][r0s], a1 = Kd[k][r1s], a2 = Kd[k][r2s], a3 = Kd[k][r3s];
                FMA2(acc[0][0], a0, b0, acc[0][0]);
                FMA2(acc[0][1], a0, b1, acc[0][1]);
                FMA2(acc[1][0], a1, b0, acc[1][0]);
                FMA2(acc[1][1], a1, b1, acc[1][1]);
                FMA2(acc[2][0], a2, b0, acc[2][0]);
                FMA2(acc[2][1], a2, b1, acc[2][1]);
                FMA2(acc[3][0], a3, b0, acc[3][0]);
                FMA2(acc[3][1], a3, b1, acc[3][1]);
            }
        }
    }

    int cnt = g_cnt[b];
    #pragma unroll
    for (int i = 0; i < 4; i++) {
        int n = row0 + wy*4 + i;
        float z0 = lo2(acc[i][0]) * scale;
        float z1 = hi2(acc[i][0]) * scale;
        float z2 = lo2(acc[i][1]) * scale;
        float z3 = hi2(acc[i][1]) * scale;
        long zb = (long)((b*NE + e)*NMAX + n) * NMAX;
        int m0 = 2*tx, m2 = 64 + 2*tx;
        *(float2*)&g_z[zb + m0] = make_float2(z0, z1);
        *(float2*)&g_z[zb + m2] = make_float2(z2, z3);
        float s = z0 * (s_maskf[m0]   * (float)(m0   != n))
                + z1 * (s_maskf[m0+1] * (float)(m0+1 != n))
                + z2 * (s_maskf[m2]   * (float)(m2   != n))
                + z3 * (s_maskf[m2+1] * (float)(m2+1 != n));
        #pragma unroll
        for (int off = 16; off > 0; off >>= 1)
            s += __shfl_xor_sync(0xffffffffu, s, off);
        if (tx == 0) {
            int mn = g_mask[base_row + n];
            float cm1 = (float)(cnt - 1);
            float denom = fmaxf(cm1, 1.0f);
            g_a[(b*NE + e)*NMAX + n] = mn ? (s / denom) : 0.0f;
            if (e == 0) g_r[base_row + n] = mn ? (cm1 / denom) : 0.0f;
        }
    }
}

// ---------------------------------------------------------------------------
// K3: gelu sum, 4 independent packed Horner chains per thread,
// 0.5*w_out folded into coefficients; O(1) range guard with erff fallback.
// Block = (8 n-rows, e, b), 128 threads; warp w owns rows 2w, 2w+1.
// ---------------------------------------------------------------------------
#define POLYACC(acc, zz, A) do { \
    ull xx, tt, pp; \
    FMA2(xx, zz, (A).x, (A).y); \
    MUL2(tt, xx, xx); \
    pp = c0_.x; \
    FMA2(pp, pp, tt, c0_.y); \
    FMA2(pp, pp, tt, c1_.x); \
    FMA2(pp, pp, tt, c1_.y); \
    FMA2(pp, pp, tt, c2_.x); \
    FMA2(pp, pp, tt, c2_.y); \
    FMA2(acc, tt, pp, acc); \
} while (0)

__global__ void __launch_bounds__(128) k_main(
        const float* __restrict__ w_self, const float* __restrict__ b_self,
        const float* __restrict__ w_out, const float* __restrict__ b_out,
        float* __restrict__ out_e, float* __restrict__ out_edge) {
    __shared__ ulonglong2 s_A[8][DS];
    __shared__ ulonglong2 s_C[DS][3];
    __shared__ float s_S0[8];
    __shared__ int s_mbi[8];
    __shared__ int s_mwsi;
    __shared__ float s_mkf[NMAX];
    int t = threadIdx.x;
    int tile = blockIdx.x, e = blockIdx.y, b = blockIdx.z;
    int rows0 = tile * 8;
    if (t < 8) s_mbi[t] = 0;
    if (t == 8) s_mwsi = 0;
    s_mkf[t] = (float)g_mask[b*NMAX + t];
    __syncthreads();
    {
        int d = t & 63;
        float ws = w_self[d];
        if (t < 64) {
            float w2 = 0.5f * w_out[d];
            s_C[d][0] = make_ulonglong2(dup2(C5*w2), dup2(C4*w2));
            s_C[d][1] = make_ulonglong2(dup2(C3*w2), dup2(C2*w2));
            s_C[d][2] = make_ulonglong2(dup2(C1*w2), dup2(C0*w2));
            atomicMax(&s_mwsi, __float_as_int(fabsf(ws)));
        }
        float u = g_u[d], v = g_v[d], bs = b_self[d];
        #pragma unroll
        for (int it = 0; it < 4; it++) {
            int row = (t >> 6) + 2*it;
            int n = rows0 + row;
            float a = g_a[(b*NE + e)*NMAX + n];
            float r = g_r[b*NMAX + n];
            float base = fmaf(a, u, fmaf(r, v, bs));
            s_A[row][d] = make_ulonglong2(dup2(ws), dup2(base));
            atomicMax(&s_mbi[row], __float_as_int(fabsf(base)));
            if (d == 0) s_S0[row] = fmaf(a, g_sc[2], fmaf(r, g_sc[3], g_sc[1]));
        }
    }
    __syncthreads();
    int lane = t & 31, w = t >> 5;
    int l0 = 2*w, l1 = 2*w + 1;
    int n0 = rows0 + l0, n1 = rows0 + l1;
    long zb0 = ((long)(b*NE + e)*NMAX + n0) * NMAX;
    long zb1 = ((long)(b*NE + e)*NMAX + n1) * NMAX;
    ull z00 = *(const ull*)&g_z[zb0 + 2*lane];
    ull z01 = *(const ull*)&g_z[zb0 + 64 + 2*lane];
    ull z10 = *(const ull*)&g_z[zb1 + 2*lane];
    ull z11 = *(const ull*)&g_z[zb1 + 64 + 2*lane];

    float mws = __int_as_float(s_mwsi);
    float zm0 = fmaxf(fmaxf(fabsf(lo2(z00)), fabsf(hi2(z00))),
                      fmaxf(fabsf(lo2(z01)), fabsf(hi2(z01))));
    float zm1 = fmaxf(fmaxf(fabsf(lo2(z10)), fabsf(hi2(z10))),
                      fmaxf(fabsf(lo2(z11)), fabsf(hi2(z11))));
    bool f0 = fmaf(zm0, mws, __int_as_float(s_mbi[l0])) > 1.25f;
    bool f1 = fmaf(zm1, mws, __int_as_float(s_mbi[l1])) > 1.25f;

    ull acc00 = 0ull, acc01 = 0ull, acc10 = 0ull, acc11 = 0ull;
    #pragma unroll 4
    for (int d = 0; d < DS; d++) {
        ulonglong2 A0 = s_A[l0][d];
        ulonglong2 A1 = s_A[l1][d];
        ulonglong2 c0_ = s_C[d][0], c1_ = s_C[d][1], c2_ = s_C[d][2];
        POLYACC(acc00, z00, A0);
        POLYACC(acc01, z01, A0);
        POLYACC(acc10, z10, A1);
        POLYACC(acc11, z11, A1);
    }
    if (f0 | f1) {
        float a00l=0.f,a00h=0.f,a01l=0.f,a01h=0.f;
        float a10l=0.f,a10h=0.f,a11l=0.f,a11h=0.f;
        for (int d = 0; d < DS; d++) {
            float w2 = 0.5f * w_out[d];
            if (f0) {
                float ws = lo2(s_A[l0][d].x), bs = lo2(s_A[l0][d].y);
                float x0 = fmaf(lo2(z00), ws, bs), x1 = fmaf(hi2(z00), ws, bs);
                float x2 = fmaf(lo2(z01), ws, bs), x3 = fmaf(hi2(z01), ws, bs);
                a00l = fmaf(w2, x0*erff(x0*0.7071067811865476f), a00l);
                a00h = fmaf(w2, x1*erff(x1*0.7071067811865476f), a00h);
                a01l = fmaf(w2, x2*erff(x2*0.7071067811865476f), a01l);
                a01h = fmaf(w2, x3*erff(x3*0.7071067811865476f), a01h);
            }
            if (f1) {
                float ws = lo2(s_A[l1][d].x), bs = lo2(s_A[l1][d].y);
                float x0 = fmaf(lo2(z10), ws, bs), x1 = fmaf(hi2(z10), ws, bs);
                float x2 = fmaf(lo2(z11), ws, bs), x3 = fmaf(hi2(z11), ws, bs);
                a10l = fmaf(w2, x0*erff(x0*0.7071067811865476f), a10l);
                a10h = fmaf(w2, x1*erff(x1*0.7071067811865476f), a10h);
                a11l = fmaf(w2, x2*erff(x2*0.7071067811865476f), a11l);
                a11h = fmaf(w2, x3*erff(x3*0.7071067811865476f), a11h);
            }
        }
        if (f0) { PACK2(acc00, a00l, a00h); PACK2(acc01, a01l, a01h); }
        if (f1) { PACK2(acc10, a10l, a10h); PACK2(acc11, a11l, a11h); }
    }

    float h1 = g_sc[0];
    float bo = b_out[0];
    float cst0 = s_S0[l0] + bo;
    float cst1 = s_S0[l1] + bo;
    int m0 = 2*lane, m2 = 64 + 2*lane;
    out_e[((long)(b*NMAX + m0  )*NMAX + n0)*NE + e] = lo2(acc00) + fmaf(lo2(z00), h1, cst0);
    out_e[((long)(b*NMAX + m0+1)*NMAX + n0)*NE + e] = hi2(acc00) + fmaf(hi2(z00), h1, cst0);
    out_e[((long)(b*NMAX + m2  )*NMAX + n0)*NE + e] = lo2(acc01) + fmaf(lo2(z01), h1, cst0);
    out_e[((long)(b*NMAX + m2+1)*NMAX + n0)*NE + e] = hi2(acc01) + fmaf(hi2(z01), h1, cst0);
    out_e[((long)(b*NMAX + m0  )*NMAX + n1)*NE + e] = lo2(acc10) + fmaf(lo2(z10), h1, cst1);
    out_e[((long)(b*NMAX + m0+1)*NMAX + n1)*NE + e] = hi2(acc10) + fmaf(hi2(z10), h1, cst1);
    out_e[((long)(b*NMAX + m2  )*NMAX + n1)*NE + e] = lo2(acc11) + fmaf(lo2(z11), h1, cst1);
    out_e[((long)(b*NMAX + m2+1)*NMAX + n1)*NE + e] = hi2(acc11) + fmaf(hi2(z11), h1, cst1);
    if (e == 0) {
        float mk0 = s_mkf[n0], mk1 = s_mkf[n1];
        float2 v;
        v = make_float2(mk0*s_mkf[m0]*(float)(n0!=m0), mk0*s_mkf[m0+1]*(float)(n0!=m0+1));
        *(float2*)&out_edge[(b*NMAX + n0)*NMAX + m0] = v;
        v = make_float2(mk0*s_mkf[m2]*(float)(n0!=m2), mk0*s_mkf[m2+1]*(float)(n0!=m2+1));
        *(float2*)&out_edge[(b*NMAX + n0)*NMAX + m2] = v;
        v = make_float2(mk1*s_mkf[m0]*(float)(n1!=m0), mk1*s_mkf[m0+1]*(float)(n1!=m0+1));
        *(float2*)&out_edge[(b*NMAX + n1)*NMAX + m0] = v;
        v = make_float2(mk1*s_mkf[m2]*(float)(n1!=m2), mk1*s_mkf[m2+1]*(float)(n1!=m2+1));
        *(float2*)&out_edge[(b*NMAX + n1)*NMAX + m2] = v;
    }
}

extern "C" void kernel_launch(void* const* d_in, const int* in_sizes, int n_in,
                              void* d_out, int out_size) {
    const float* x      = (const float*)d_in[0];
    const int*   batch  = (const int*)  d_in[1];
    const float* q      = (const float*)d_in[2];
    const float* w_attn = (const float*)d_in[3];
    const float* b_attn = (const float*)d_in[4];
    const float* w_node = (const float*)d_in[5];
    const float* b_node = (const float*)d_in[6];
    const float* w_phi  = (const float*)d_in[7];
    const float* b_phi  = (const float*)d_in[8];
    const float* w_ctx  = (const float*)d_in[9];
    const float* w_self = (const float*)d_in[10];
    const float* b_self = (const float*)d_in[11];
    const float* w_out  = (const float*)d_in[12];
    const float* b_out  = (const float*)d_in[13];
    float* out = (float*)d_out;

    k_setup<<<1, 1024>>>(batch, q, w_phi, b_phi, w_ctx, w_self, b_self, w_out, out + OFF_MASK);
    k_projx<<<dim3(21, 16), 256>>>(x, w_attn, b_attn, w_node, b_node, out + OFF_XHAT);
    k_zrows<<<dim3(8, NE, BATCHES), 128>>>();
    k_main<<<dim3(16, NE, BATCHES), 128>>>(w_self, b_self, w_out, b_out,
                                           out + OFF_EHAT, out + OFF_EDGE);
}

// round 6
// speedup vs baseline: 1.2412x; 1.2397x over previous
#include <cuda_runtime.h>
#include <math.h>

#define BATCHES 8
#define NMAX    128
#define PE      64
#define NE      5
#define DS      64
#define NF      8
#define TOTAL   (BATCHES*NMAX)
#define PROJC   (4*NE*PE)
#define ZCOUNT  (BATCHES*NE*NMAX*NMAX)
#define NROWS   (BATCHES*NE*NMAX)

#define OFF_EHAT 0
#define OFF_XHAT (BATCHES*NMAX*NMAX*NE)
#define OFF_EDGE (OFF_XHAT + TOTAL*NF)
#define OFF_MASK (OFF_EDGE + BATCHES*NMAX*NMAX)

typedef unsigned long long ull;

__device__ float  g_proj[TOTAL*PROJC];
__device__ float  g_z[ZCOUNT];
__device__ float  g_a[NROWS];
__device__ float  g_zmax[NROWS];
__device__ float  g_r[BATCHES*NMAX];
__device__ int    g_node[BATCHES*NMAX];
__device__ int    g_mask[BATCHES*NMAX];
__device__ int    g_cnt[BATCHES];
__device__ float  g_coef[BATCHES];
__device__ float  g_u[DS];
__device__ float  g_v[DS];
__device__ float  g_mws;
__device__ float  g_dct[14*14];
__device__ float  g_cheb[14];

#define FMA2(d,a,b,c) asm("fma.rn.f32x2 %0, %1, %2, %3;" : "=l"(d) : "l"(a), "l"(b), "l"(c))
#define MUL2(d,a,b)   asm("mul.rn.f32x2 %0, %1, %2;" : "=l"(d) : "l"(a), "l"(b))
#define ADD2(d,a,b)   asm("add.rn.f32x2 %0, %1, %2;" : "=l"(d) : "l"(a), "l"(b))
#define PACK2(d,lo,hi) asm("mov.b64 %0, {%1, %2};" : "=l"(d) : "r"(__float_as_uint(lo)), "r"(__float_as_uint(hi)))

__device__ __forceinline__ ull dup2(float v) { ull d; PACK2(d, v, v); return d; }
__device__ __forceinline__ float lo2(ull v) { return __uint_as_float((unsigned int)v); }
__device__ __forceinline__ float hi2(ull v) { return __uint_as_float((unsigned int)(v >> 32)); }

// erf(x/sqrt(2)) = x * (C0 + C1 x^2 + ... + C5 x^10), |x|<=1.5
#define C0  0.7978845608028654f
#define C1 (-0.13298076013381092f)
#define C2  0.019947114020071635f
#define C3 (-0.0023746564309608790f)
#define C4  2.3087512708529163e-4f
#define C5 (-1.8888357703977833e-5f)
#define PI_F 3.14159265358979323846f

// ---------------------------------------------------------------------------
// K0: dense map, counts, coef, u/v, mws, Chebyshev node/DCT tables, mask out.
// ---------------------------------------------------------------------------
__global__ void k_setup(const int* __restrict__ batch, const float* __restrict__ q,
                        const float* __restrict__ w_phi, const float* __restrict__ b_phi,
                        const float* __restrict__ w_ctx,
                        const float* __restrict__ w_self,
                        float* __restrict__ out_mask) {
    __shared__ int s_start[BATCHES];
    __shared__ int s_cnt[BATCHES];
    int t = threadIdx.x;
    if (t < BATCHES) { s_cnt[t] = 0; s_start[t] = 0; }
    g_node[t] = -1;
    g_mask[t] = 0;
    out_mask[t] = 0.0f;
    // Chebyshev tables: nodes t_j = cos((2j+1)pi/28); M[k][j] = sk*cos(k*(2j+1)pi/28)
    if (t < 196) {
        int k = t / 14, j = t % 14;
        float th = (float)(2*j + 1) * (PI_F / 28.0f);
        float sk = (k == 0) ? (1.0f/14.0f) : (2.0f/14.0f);
        g_dct[t] = sk * cosf((float)k * th);
        if (k == 0) g_cheb[j] = cosf(th);
    }
    __syncthreads();
    int b = batch[t];
    if (t == 0 || batch[t-1] != b) s_start[b] = t;
    atomicAdd(&s_cnt[b], 1);
    if (t < DS) {
        float u = 0.f, v = 0.f;
        #pragma unroll 8
        for (int k = 0; k < DS; k++) {
            float wc = w_ctx[k*DS + t];
            u = fmaf(w_phi[k], wc, u);
            v = fmaf(b_phi[k], wc, v);
        }
        g_u[t] = u; g_v[t] = v;
    }
    __syncthreads();
    int pos = t - s_start[b];
    int di = b*NMAX + pos;
    g_node[di] = t;
    g_mask[di] = 1;
    out_mask[di] = 1.0f;
    if (t < BATCHES) {
        g_cnt[t] = s_cnt[t];
        float qq = q[t];
        float c = cosf(6.283185307179586f*qq);
        float s = sinf(6.283185307179586f*qq);
        g_coef[t] = (2.0f - c) / s;
    }
    if (t < 32) {
        float m = fmaxf(fabsf(w_self[t]), fabsf(w_self[t+32]));
        #pragma unroll
        for (int off = 16; off > 0; off >>= 1)
            m = fmaxf(m, __shfl_xor_sync(0xffffffffu, m, off));
        if (t == 0) g_mws = m;
    }
}

// ---------------------------------------------------------------------------
// K1: proj = x @ w_attn + b_attn (dense layout, packed f32x2) + x_hat.
// ---------------------------------------------------------------------------
__global__ void k_projx(const float* __restrict__ x, const float* __restrict__ w,
                        const float* __restrict__ bias,
                        const float* __restrict__ w_node, const float* __restrict__ b_node,
                        float* __restrict__ out_xhat) {
    if (blockIdx.x == 20) {
        int base = blockIdx.y * 512;
        #pragma unroll
        for (int l = 0; l < 2; l++) {
            int id = base + threadIdx.x + l*256;
            int node = id / NF, f = id % NF;
            float acc = 0.f;
            #pragma unroll 8
            for (int k = 0; k < PE; k++)
                acc = fmaf(__ldg(&x[node*PE + k]), __ldg(&w_node[k*NF + f]), acc);
            out_xhat[id] = acc + b_node[f];
        }
        return;
    }
    __shared__ ull Ad[64][64];
    __shared__ ull Wp[64][32];
    int tid = threadIdx.x;
    int tx = tid & 15, ty = tid >> 4;
    int row0 = blockIdx.y * 64;
    int col0 = blockIdx.x * 64;
    #pragma unroll
    for (int l = 0; l < 4; l++) {
        int e = tid + l*256;
        int r = e >> 4, kq = (e & 15) * 4;
        int node = g_node[row0 + r];
        float4 v = make_float4(0.f,0.f,0.f,0.f);
        if (node >= 0) v = *(const float4*)&x[node*PE + kq];
        Ad[r][kq+0] = dup2(v.x);
        Ad[r][kq+1] = dup2(v.y);
        Ad[r][kq+2] = dup2(v.z);
        Ad[r][kq+3] = dup2(v.w);
    }
    #pragma unroll
    for (int l = 0; l < 4; l++) {
        int e = tid + l*256;
        int k = e >> 4, cq = (e & 15) * 4;
        float4 v = *(const float4*)&w[k*PROJC + col0 + cq];
        ull p0, p1;
        PACK2(p0, v.x, v.y);
        PACK2(p1, v.z, v.w);
        Wp[k][cq/2]   = p0;
        Wp[k][cq/2+1] = p1;
    }
    __syncthreads();
    ull acc[4][2];
    #pragma unroll
    for (int i = 0; i < 4; i++) { acc[i][0] = 0ull; acc[i][1] = 0ull; }
    #pragma unroll 4
    for (int kk = 0; kk < 64; kk += 2) {
        ulonglong2 ai[4];
        #pragma unroll
        for (int i = 0; i < 4; i++)
            ai[i] = *(const ulonglong2*)&Ad[ty + 16*i][kk];
        ull b00 = Wp[kk][tx],   b10 = Wp[kk][tx+16];
        ull b01 = Wp[kk+1][tx], b11 = Wp[kk+1][tx+16];
        #pragma unroll
        for (int i = 0; i < 4; i++) {
            FMA2(acc[i][0], ai[i].x, b00, acc[i][0]);
            FMA2(acc[i][0], ai[i].y, b01, acc[i][0]);
            FMA2(acc[i][1], ai[i].x, b10, acc[i][1]);
            FMA2(acc[i][1], ai[i].y, b11, acc[i][1]);
        }
    }
    #pragma unroll
    for (int i = 0; i < 4; i++) {
        int r = row0 + ty + 16*i;
        int node = g_node[r];
        #pragma unroll
        for (int j = 0; j < 2; j++) {
            int cp = tx + 16*j;
            int c = col0 + 2*cp;
            float v0 = 0.f, v1 = 0.f;
            if (node >= 0) {
                v0 = lo2(acc[i][j]) + bias[c];
                v1 = hi2(acc[i][j]) + bias[c+1];
            }
            *(float2*)&g_proj[r*PROJC + c] = make_float2(v0, v1);
        }
    }
}

// ---------------------------------------------------------------------------
// K2: z GEMM (packed f32x2, XOR-swizzled smem) + masked row means + row |z|max.
// ---------------------------------------------------------------------------
__global__ void __launch_bounds__(128) k_zrows() {
    __shared__ ull Kd[64][17];
    __shared__ float Qt[64][130];
    __shared__ float s_maskf[NMAX];
    const float scale = 0.05590169943749474f;
    int tid = threadIdx.x;
    int tx = tid & 31, wy = tid >> 5;
    int tile = blockIdx.x, e = blockIdx.y, b = blockIdx.z;
    int row0 = tile * 16;
    int base_row = b * NMAX;
    float coef = g_coef[b];
    s_maskf[tid] = (float)g_mask[base_row + tid];

    ull acc[4][2];
    #pragma unroll
    for (int i = 0; i < 4; i++) { acc[i][0] = 0ull; acc[i][1] = 0ull; }

    #pragma unroll
    for (int p = 0; p < 2; p++) {
        float cs = p ? coef : 1.0f;
        int koff = (p ? 2*NE*PE : 0) + e*PE;
        int qoff = (p ? 3*NE*PE : NE*PE) + e*PE;
        if (p) __syncthreads();
        #pragma unroll
        for (int l = 0; l < 2; l++) {
            int e4 = tid + l*128;
            int r = e4 >> 4;
            int kq = (e4 & 15) * 4;
            int sw = (kq >> 4) & 3;
            float4 v = *(const float4*)&g_proj[(base_row + row0 + r)*PROJC + koff + kq];
            Kd[kq+0][r ^ sw] = dup2(v.x * cs);
            Kd[kq+1][r ^ sw] = dup2(v.y * cs);
            Kd[kq+2][r ^ sw] = dup2(v.z * cs);
            Kd[kq+3][r ^ sw] = dup2(v.w * cs);
        }
        #pragma unroll
        for (int l = 0; l < 16; l++) {
            int e4 = tid + l*128;
            int m = e4 >> 4;
            int kq = (e4 & 15) * 4;
            int ms = m ^ (((kq >> 4) & 3) << 1);
            float4 v = *(const float4*)&g_proj[(base_row + m)*PROJC + qoff + kq];
            Qt[kq+0][ms] = v.x;
            Qt[kq+1][ms] = v.y;
            Qt[kq+2][ms] = v.z;
            Qt[kq+3][ms] = v.w;
        }
        __syncthreads();
        #pragma unroll
        for (int kg = 0; kg < 4; kg++) {
            int c0 = (2*tx) ^ (kg << 1);
            int r0s = (4*wy + 0) ^ kg;
            int r1s = (4*wy + 1) ^ kg;
            int r2s = (4*wy + 2) ^ kg;
            int r3s = (4*wy + 3) ^ kg;
            #pragma unroll
            for (int kk = 0; kk < 16; kk++) {
                int k = kg*16 + kk;
                ull b0 = *(const ull*)&Qt[k][c0];
                ull b1 = *(const ull*)&Qt[k][c0 + 64];
                ull a0 = Kd[k][r0s], a1 = Kd[k][r1s], a2 = Kd[k][r2s], a3 = Kd[k][r3s];
                FMA2(acc[0][0], a0, b0, acc[0][0]);
                FMA2(acc[0][1], a0, b1, acc[0][1]);
                FMA2(acc[1][0], a1, b0, acc[1][0]);
                FMA2(acc[1][1], a1, b1, acc[1][1]);
                FMA2(acc[2][0], a2, b0, acc[2][0]);
                FMA2(acc[2][1], a2, b1, acc[2][1]);
                FMA2(acc[3][0], a3, b0, acc[3][0]);
                FMA2(acc[3][1], a3, b1, acc[3][1]);
            }
        }
    }

    int cnt = g_cnt[b];
    #pragma unroll
    for (int i = 0; i < 4; i++) {
        int n = row0 + wy*4 + i;
        float z0 = lo2(acc[i][0]) * scale;
        float z1 = hi2(acc[i][0]) * scale;
        float z2 = lo2(acc[i][1]) * scale;
        float z3 = hi2(acc[i][1]) * scale;
        long zb = (long)((b*NE + e)*NMAX + n) * NMAX;
        int m0 = 2*tx, m2 = 64 + 2*tx;
        *(float2*)&g_z[zb + m0] = make_float2(z0, z1);
        *(float2*)&g_z[zb + m2] = make_float2(z2, z3);
        float s = z0 * (s_maskf[m0]   * (float)(m0   != n))
                + z1 * (s_maskf[m0+1] * (float)(m0+1 != n))
                + z2 * (s_maskf[m2]   * (float)(m2   != n))
                + z3 * (s_maskf[m2+1] * (float)(m2+1 != n));
        float zm = fmaxf(fmaxf(fabsf(z0), fabsf(z1)), fmaxf(fabsf(z2), fabsf(z3)));
        #pragma unroll
        for (int off = 16; off > 0; off >>= 1) {
            s += __shfl_xor_sync(0xffffffffu, s, off);
            zm = fmaxf(zm, __shfl_xor_sync(0xffffffffu, zm, off));
        }
        if (tx == 0) {
            int ridx = (b*NE + e)*NMAX + n;
            int mn = g_mask[base_row + n];
            float cm1 = (float)(cnt - 1);
            float denom = fmaxf(cm1, 1.0f);
            g_a[ridx] = mn ? (s / denom) : 0.0f;
            g_zmax[ridx] = zm;
            if (e == 0) g_r[base_row + n] = mn ? (cm1 / denom) : 0.0f;
        }
    }
}

// ---------------------------------------------------------------------------
// K3: per-row degree-13 Chebyshev compression of the gelu sum.
// One warp per row (b,e,n): 14 nodal sums over d -> DCT -> Clenshaw per col.
// ---------------------------------------------------------------------------
__global__ void __launch_bounds__(256) k_main(
        const float* __restrict__ w_self, const float* __restrict__ b_self,
        const float* __restrict__ w_out, const float* __restrict__ b_out,
        float* __restrict__ out_e, float* __restrict__ out_edge) {
    __shared__ float s_ws[DS], s_w2[DS], s_bs[DS], s_u[DS], s_v[DS];
    __shared__ float s_mkf[NMAX];
    int t = threadIdx.x;
    int e = blockIdx.y, b = blockIdx.z;
    if (t < DS) {
        s_ws[t] = w_self[t];
        s_w2[t] = 0.5f * w_out[t];
        s_bs[t] = b_self[t];
        s_u[t]  = g_u[t];
        s_v[t]  = g_v[t];
    }
    if (t < NMAX) s_mkf[t] = (float)g_mask[b*NMAX + t];
    __syncthreads();

    int lane = t & 31, w = t >> 5;
    int n = blockIdx.x * 8 + w;
    int ridx = (b*NE + e)*NMAX + n;
    long rowz = (long)ridx * NMAX;
    float alpha = g_a[ridx];
    float rho   = g_r[b*NMAX + n];
    float zmax  = fmaxf(g_zmax[ridx], 1e-20f);
    float bo    = b_out[0];

    // per-lane d pair
    float ws0 = s_ws[lane],    ws1 = s_ws[lane+32];
    float w20 = s_w2[lane],    w21 = s_w2[lane+32];
    float a0 = fmaf(alpha, s_u[lane],    fmaf(rho, s_v[lane],    s_bs[lane]));
    float a1 = fmaf(alpha, s_u[lane+32], fmaf(rho, s_v[lane+32], s_bs[lane+32]));
    float amax = fmaxf(fabsf(a0), fabsf(a1));
    #pragma unroll
    for (int off = 16; off > 0; off >>= 1)
        amax = fmaxf(amax, __shfl_xor_sync(0xffffffffu, amax, off));
    bool fb = fmaf(zmax, g_mws, amax) > 1.5f;

    if (!fb) {
        // nodal sums at z_j = zmax * cheb_j (14 nodes, 7 packed pairs)
        const ull k0 = dup2(C0), k1 = dup2(C1), k2 = dup2(C2);
        const ull k3 = dup2(C3), k4 = dup2(C4), k5 = dup2(C5);
        ull zn[7], acc[7];
        #pragma unroll
        for (int j = 0; j < 7; j++) {
            PACK2(zn[j], zmax * g_cheb[2*j], zmax * g_cheb[2*j+1]);
            acc[j] = 0ull;
        }
        #pragma unroll
        for (int dd = 0; dd < 2; dd++) {
            ull wsd = dup2(dd ? ws1 : ws0);
            ull ad  = dup2(dd ? a1  : a0);
            ull w2d = dup2(dd ? w21 : w20);
            #pragma unroll
            for (int j = 0; j < 7; j++) {
                ull xx, tt, p, h;
                FMA2(xx, wsd, zn[j], ad);
                MUL2(tt, xx, xx);
                p = k5;
                FMA2(p, p, tt, k4);
                FMA2(p, p, tt, k3);
                FMA2(p, p, tt, k2);
                FMA2(p, p, tt, k1);
                FMA2(p, p, tt, k0);
                FMA2(h, tt, p, xx);          // h = xx + xx^2*E = gelu*2/wo_d
                FMA2(acc[j], w2d, h, acc[j]);
            }
        }
        // reduce across lanes
        #pragma unroll
        for (int off = 16; off > 0; off >>= 1) {
            #pragma unroll
            for (int j = 0; j < 7; j++) {
                ull o = __shfl_xor_sync(0xffffffffu, acc[j], off);
                ADD2(acc[j], acc[j], o);
            }
        }
        // DCT: lane k<14 computes c_k
        float c = 0.f;
        if (lane < 14) {
            #pragma unroll
            for (int j = 0; j < 7; j++) {
                c = fmaf(__ldg(&g_dct[lane*14 + 2*j]),   lo2(acc[j]), c);
                c = fmaf(__ldg(&g_dct[lane*14 + 2*j+1]), hi2(acc[j]), c);
            }
        }
        ull ck[14];
        #pragma unroll
        for (int k = 0; k < 14; k++)
            ck[k] = dup2(__shfl_sync(0xffffffffu, c, k));

        // Clenshaw per packed column pair
        float rinv = 1.0f / zmax;
        ull rinv2 = dup2(rinv);
        ull negone = dup2(-1.0f);
        #pragma unroll
        for (int pi = 0; pi < 2; pi++) {
            int m = 2*lane + 64*pi;
            ull z2 = *(const ull*)&g_z[rowz + m];
            ull s2, s2x;
            MUL2(s2, z2, rinv2);
            ADD2(s2x, s2, s2);
            ull b1 = 0ull, b2 = 0ull;
            #pragma unroll
            for (int k = 13; k >= 1; k--) {
                ull nb;
                FMA2(nb, s2x, b1, ck[k]);
                FMA2(nb, b2, negone, nb);
                b2 = b1; b1 = nb;
            }
            ull f;
            FMA2(f, s2, b1, ck[0]);
            FMA2(f, b2, negone, f);
            out_e[((long)(b*NMAX + m  )*NMAX + n)*NE + e] = lo2(f) + bo;
            out_e[((long)(b*NMAX + m+1)*NMAX + n)*NE + e] = hi2(f) + bo;
        }
    } else {
        // exact fallback for the whole row (rare)
        float2 za = *(const float2*)&g_z[rowz + 2*lane];
        float2 zb = *(const float2*)&g_z[rowz + 2*lane + 64];
        float e0 = 0.f, e1 = 0.f, e2 = 0.f, e3 = 0.f;
        for (int d = 0; d < DS; d++) {
            float ad = fmaf(alpha, s_u[d], fmaf(rho, s_v[d], s_bs[d]));
            float ws = s_ws[d], w2 = s_w2[d];
            float x;
            x = fmaf(za.x, ws, ad); e0 = fmaf(w2, x*(1.f + erff(x*0.7071067811865476f)), e0);
            x = fmaf(za.y, ws, ad); e1 = fmaf(w2, x*(1.f + erff(x*0.7071067811865476f)), e1);
            x = fmaf(zb.x, ws, ad); e2 = fmaf(w2, x*(1.f + erff(x*0.7071067811865476f)), e2);
            x = fmaf(zb.y, ws, ad); e3 = fmaf(w2, x*(1.f + erff(x*0.7071067811865476f)), e3);
        }
        int m0 = 2*lane, m2 = 2*lane + 64;
        out_e[((long)(b*NMAX + m0  )*NMAX + n)*NE + e] = e0 + bo;
        out_e[((long)(b*NMAX + m0+1)*NMAX + n)*NE + e] = e1 + bo;
        out_e[((long)(b*NMAX + m2  )*NMAX + n)*NE + e] = e2 + bo;
        out_e[((long)(b*NMAX + m2+1)*NMAX + n)*NE + e] = e3 + bo;
    }

    if (e == 0) {
        int m0 = 2*lane, m2 = 2*lane + 64;
        float mkn = s_mkf[n];
        float2 v;
        v = make_float2(mkn*s_mkf[m0]*(float)(n != m0), mkn*s_mkf[m0+1]*(float)(n != m0+1));
        *(float2*)&out_edge[(b*NMAX + n)*NMAX + m0] = v;
        v = make_float2(mkn*s_mkf[m2]*(float)(n != m2), mkn*s_mkf[m2+1]*(float)(n != m2+1));
        *(float2*)&out_edge[(b*NMAX + n)*NMAX + m2] = v;
    }
}

extern "C" void kernel_launch(void* const* d_in, const int* in_sizes, int n_in,
                              void* d_out, int out_size) {
    const float* x      = (const float*)d_in[0];
    const int*   batch  = (const int*)  d_in[1];
    const float* q      = (const float*)d_in[2];
    const float* w_attn = (const float*)d_in[3];
    const float* b_attn = (const float*)d_in[4];
    const float* w_node = (const float*)d_in[5];
    const float* b_node = (const float*)d_in[6];
    const float* w_phi  = (const float*)d_in[7];
    const float* b_phi  = (const float*)d_in[8];
    const float* w_ctx  = (const float*)d_in[9];
    const float* w_self = (const float*)d_in[10];
    const float* b_self = (const float*)d_in[11];
    const float* w_out  = (const float*)d_in[12];
    const float* b_out  = (const float*)d_in[13];
    float* out = (float*)d_out;

    k_setup<<<1, 1024>>>(batch, q, w_phi, b_phi, w_ctx, w_self, out + OFF_MASK);
    k_projx<<<dim3(21, 16), 256>>>(x, w_attn, b_attn, w_node, b_node, out + OFF_XHAT);
    k_zrows<<<dim3(8, NE, BATCHES), 128>>>();
    k_main<<<dim3(16, NE, BATCHES), 256>>>(w_self, b_self, w_out, b_out,
                                           out + OFF_EHAT, out + OFF_EDGE);
}

// round 7
// speedup vs baseline: 1.2541x; 1.0104x over previous
#include <cuda_runtime.h>
#include <math.h>

#define BATCHES 8
#define NMAX    128
#define PE      64
#define NE      5
#define DS      64
#define NF      8
#define TOTAL   (BATCHES*NMAX)
#define PROJC   (4*NE*PE)
#define ZCOUNT  (BATCHES*NE*NMAX*NMAX)
#define NROWS   (BATCHES*NE*NMAX)

#define OFF_EHAT 0
#define OFF_XHAT (BATCHES*NMAX*NMAX*NE)
#define OFF_EDGE (OFF_XHAT + TOTAL*NF)
#define OFF_MASK (OFF_EDGE + BATCHES*NMAX*NMAX)

typedef unsigned long long ull;

__device__ float  g_proj[TOTAL*PROJC];
__device__ float  g_z[ZCOUNT];
__device__ float  g_ck[NROWS*16];     // 14 cheb coeffs + rinv + pad per row
__device__ int    g_node[BATCHES*NMAX];
__device__ int    g_mask[BATCHES*NMAX];
__device__ int    g_cnt[BATCHES];
__device__ float  g_coef[BATCHES];
__device__ float  g_u[DS];
__device__ float  g_v[DS];
__device__ float  g_dct[14*14];
__device__ float  g_cheb[14];

#define FMA2(d,a,b,c) asm("fma.rn.f32x2 %0, %1, %2, %3;" : "=l"(d) : "l"(a), "l"(b), "l"(c))
#define MUL2(d,a,b)   asm("mul.rn.f32x2 %0, %1, %2;" : "=l"(d) : "l"(a), "l"(b))
#define ADD2(d,a,b)   asm("add.rn.f32x2 %0, %1, %2;" : "=l"(d) : "l"(a), "l"(b))
#define PACK2(d,lo,hi) asm("mov.b64 %0, {%1, %2};" : "=l"(d) : "r"(__float_as_uint(lo)), "r"(__float_as_uint(hi)))

__device__ __forceinline__ ull dup2(float v) { ull d; PACK2(d, v, v); return d; }
__device__ __forceinline__ float lo2(ull v) { return __uint_as_float((unsigned int)v); }
__device__ __forceinline__ float hi2(ull v) { return __uint_as_float((unsigned int)(v >> 32)); }

// erf(x/sqrt(2)) = x * (C0 + C1 x^2 + ... + C5 x^10), |x|<=1.5
#define C0  0.7978845608028654f
#define C1 (-0.13298076013381092f)
#define C2  0.019947114020071635f
#define C3 (-0.0023746564309608790f)
#define C4  2.3087512708529163e-4f
#define C5 (-1.8888357703977833e-5f)
#define PI_F 3.14159265358979323846f

// ---------------------------------------------------------------------------
// K0: dense map, counts, coef, u/v, Chebyshev tables, mask output.
// ---------------------------------------------------------------------------
__global__ void k_setup(const int* __restrict__ batch, const float* __restrict__ q,
                        const float* __restrict__ w_phi, const float* __restrict__ b_phi,
                        const float* __restrict__ w_ctx,
                        float* __restrict__ out_mask) {
    __shared__ int s_start[BATCHES];
    __shared__ int s_cnt[BATCHES];
    int t = threadIdx.x;
    if (t < BATCHES) { s_cnt[t] = 0; s_start[t] = 0; }
    g_node[t] = -1;
    g_mask[t] = 0;
    out_mask[t] = 0.0f;
    if (t < 196) {
        int k = t / 14, j = t % 14;
        float th = (float)(2*j + 1) * (PI_F / 28.0f);
        float sk = (k == 0) ? (1.0f/14.0f) : (2.0f/14.0f);
        g_dct[t] = sk * cosf((float)k * th);
        if (k == 0) g_cheb[j] = cosf(th);
    }
    __syncthreads();
    int b = batch[t];
    if (t == 0 || batch[t-1] != b) s_start[b] = t;
    atomicAdd(&s_cnt[b], 1);
    if (t < DS) {
        float u = 0.f, v = 0.f;
        #pragma unroll 8
        for (int k = 0; k < DS; k++) {
            float wc = w_ctx[k*DS + t];
            u = fmaf(w_phi[k], wc, u);
            v = fmaf(b_phi[k], wc, v);
        }
        g_u[t] = u; g_v[t] = v;
    }
    __syncthreads();
    int pos = t - s_start[b];
    int di = b*NMAX + pos;
    g_node[di] = t;
    g_mask[di] = 1;
    out_mask[di] = 1.0f;
    if (t < BATCHES) {
        g_cnt[t] = s_cnt[t];
        float qq = q[t];
        float c = cosf(6.283185307179586f*qq);
        float s = sinf(6.283185307179586f*qq);
        g_coef[t] = (2.0f - c) / s;
    }
}

// ---------------------------------------------------------------------------
// K1: proj = x @ w_attn + b_attn (dense layout, packed f32x2) + x_hat.
// ---------------------------------------------------------------------------
__global__ void k_projx(const float* __restrict__ x, const float* __restrict__ w,
                        const float* __restrict__ bias,
                        const float* __restrict__ w_node, const float* __restrict__ b_node,
                        float* __restrict__ out_xhat) {
    if (blockIdx.x == 20) {
        int base = blockIdx.y * 512;
        #pragma unroll
        for (int l = 0; l < 2; l++) {
            int id = base + threadIdx.x + l*256;
            int node = id / NF, f = id % NF;
            float acc = 0.f;
            #pragma unroll 8
            for (int k = 0; k < PE; k++)
                acc = fmaf(__ldg(&x[node*PE + k]), __ldg(&w_node[k*NF + f]), acc);
            out_xhat[id] = acc + b_node[f];
        }
        return;
    }
    __shared__ ull Ad[64][64];
    __shared__ ull Wp[64][32];
    int tid = threadIdx.x;
    int tx = tid & 15, ty = tid >> 4;
    int row0 = blockIdx.y * 64;
    int col0 = blockIdx.x * 64;
    #pragma unroll
    for (int l = 0; l < 4; l++) {
        int e = tid + l*256;
        int r = e >> 4, kq = (e & 15) * 4;
        int node = g_node[row0 + r];
        float4 v = make_float4(0.f,0.f,0.f,0.f);
        if (node >= 0) v = *(const float4*)&x[node*PE + kq];
        Ad[r][kq+0] = dup2(v.x);
        Ad[r][kq+1] = dup2(v.y);
        Ad[r][kq+2] = dup2(v.z);
        Ad[r][kq+3] = dup2(v.w);
    }
    #pragma unroll
    for (int l = 0; l < 4; l++) {
        int e = tid + l*256;
        int k = e >> 4, cq = (e & 15) * 4;
        float4 v = *(const float4*)&w[k*PROJC + col0 + cq];
        ull p0, p1;
        PACK2(p0, v.x, v.y);
        PACK2(p1, v.z, v.w);
        Wp[k][cq/2]   = p0;
        Wp[k][cq/2+1] = p1;
    }
    __syncthreads();
    ull acc[4][2];
    #pragma unroll
    for (int i = 0; i < 4; i++) { acc[i][0] = 0ull; acc[i][1] = 0ull; }
    #pragma unroll 4
    for (int kk = 0; kk < 64; kk += 2) {
        ulonglong2 ai[4];
        #pragma unroll
        for (int i = 0; i < 4; i++)
            ai[i] = *(const ulonglong2*)&Ad[ty + 16*i][kk];
        ull b00 = Wp[kk][tx],   b10 = Wp[kk][tx+16];
        ull b01 = Wp[kk+1][tx], b11 = Wp[kk+1][tx+16];
        #pragma unroll
        for (int i = 0; i < 4; i++) {
            FMA2(acc[i][0], ai[i].x, b00, acc[i][0]);
            FMA2(acc[i][0], ai[i].y, b01, acc[i][0]);
            FMA2(acc[i][1], ai[i].x, b10, acc[i][1]);
            FMA2(acc[i][1], ai[i].y, b11, acc[i][1]);
        }
    }
    #pragma unroll
    for (int i = 0; i < 4; i++) {
        int r = row0 + ty + 16*i;
        int node = g_node[r];
        #pragma unroll
        for (int j = 0; j < 2; j++) {
            int cp = tx + 16*j;
            int c = col0 + 2*cp;
            float v0 = 0.f, v1 = 0.f;
            if (node >= 0) {
                v0 = lo2(acc[i][j]) + bias[c];
                v1 = hi2(acc[i][j]) + bias[c+1];
            }
            *(float2*)&g_proj[r*PROJC + c] = make_float2(v0, v1);
        }
    }
}

// ---------------------------------------------------------------------------
// K2: z GEMM + row means/zmax + per-row Chebyshev coefficients (fused).
// Epilogue smem aliases the dead GEMM tiles (union) to stay under 48KB.
// ---------------------------------------------------------------------------
struct SmemGemm { ull Kd[64][17]; float Qt[64][130]; };
struct SmemEpi  {
    float a[16][64];            // per-row gelu offsets a_d
    float nod[16][16];          // nodal sums (14 used)
    ull   ws2[64];              // dup2(w_self)
    ull   w2d[64];              // dup2(0.5*w_out)
    float alpha[16], rho[16], zmax[16];
};

__global__ void __launch_bounds__(128) k_zrows(
        const float* __restrict__ w_self, const float* __restrict__ b_self,
        const float* __restrict__ w_out) {
    __shared__ union { SmemGemm g; SmemEpi e; } su;
    __shared__ float s_maskf[NMAX];
    const float scale = 0.05590169943749474f;
    int tid = threadIdx.x;
    int tx = tid & 31, wy = tid >> 5;
    int tile = blockIdx.x, e = blockIdx.y, b = blockIdx.z;
    int row0 = tile * 16;
    int base_row = b * NMAX;
    float coef = g_coef[b];
    s_maskf[tid] = (float)g_mask[base_row + tid];

    ull acc[4][2];
    #pragma unroll
    for (int i = 0; i < 4; i++) { acc[i][0] = 0ull; acc[i][1] = 0ull; }

    #pragma unroll
    for (int p = 0; p < 2; p++) {
        float cs = p ? coef : 1.0f;
        int koff = (p ? 2*NE*PE : 0) + e*PE;
        int qoff = (p ? 3*NE*PE : NE*PE) + e*PE;
        if (p) __syncthreads();
        #pragma unroll
        for (int l = 0; l < 2; l++) {
            int e4 = tid + l*128;
            int r = e4 >> 4;
            int kq = (e4 & 15) * 4;
            int sw = (kq >> 4) & 3;
            float4 v = *(const float4*)&g_proj[(base_row + row0 + r)*PROJC + koff + kq];
            su.g.Kd[kq+0][r ^ sw] = dup2(v.x * cs);
            su.g.Kd[kq+1][r ^ sw] = dup2(v.y * cs);
            su.g.Kd[kq+2][r ^ sw] = dup2(v.z * cs);
            su.g.Kd[kq+3][r ^ sw] = dup2(v.w * cs);
        }
        #pragma unroll
        for (int l = 0; l < 16; l++) {
            int e4 = tid + l*128;
            int m = e4 >> 4;
            int kq = (e4 & 15) * 4;
            int ms = m ^ (((kq >> 4) & 3) << 1);
            float4 v = *(const float4*)&g_proj[(base_row + m)*PROJC + qoff + kq];
            su.g.Qt[kq+0][ms] = v.x;
            su.g.Qt[kq+1][ms] = v.y;
            su.g.Qt[kq+2][ms] = v.z;
            su.g.Qt[kq+3][ms] = v.w;
        }
        __syncthreads();
        #pragma unroll
        for (int kg = 0; kg < 4; kg++) {
            int c0 = (2*tx) ^ (kg << 1);
            int r0s = (4*wy + 0) ^ kg;
            int r1s = (4*wy + 1) ^ kg;
            int r2s = (4*wy + 2) ^ kg;
            int r3s = (4*wy + 3) ^ kg;
            #pragma unroll
            for (int kk = 0; kk < 16; kk++) {
                int k = kg*16 + kk;
                ull b0 = *(const ull*)&su.g.Qt[k][c0];
                ull b1 = *(const ull*)&su.g.Qt[k][c0 + 64];
                ull a0 = su.g.Kd[k][r0s], a1 = su.g.Kd[k][r1s];
                ull a2 = su.g.Kd[k][r2s], a3 = su.g.Kd[k][r3s];
                FMA2(acc[0][0], a0, b0, acc[0][0]);
                FMA2(acc[0][1], a0, b1, acc[0][1]);
                FMA2(acc[1][0], a1, b0, acc[1][0]);
                FMA2(acc[1][1], a1, b1, acc[1][1]);
                FMA2(acc[2][0], a2, b0, acc[2][0]);
                FMA2(acc[2][1], a2, b1, acc[2][1]);
                FMA2(acc[3][0], a3, b0, acc[3][0]);
                FMA2(acc[3][1], a3, b1, acc[3][1]);
            }
        }
    }
    __syncthreads();    // GEMM tiles dead; epilogue may alias su

    int cnt = g_cnt[b];
    #pragma unroll
    for (int i = 0; i < 4; i++) {
        int n = row0 + wy*4 + i;
        float z0 = lo2(acc[i][0]) * scale;
        float z1 = hi2(acc[i][0]) * scale;
        float z2 = lo2(acc[i][1]) * scale;
        float z3 = hi2(acc[i][1]) * scale;
        long zb = (long)((b*NE + e)*NMAX + n) * NMAX;
        int m0 = 2*tx, m2 = 64 + 2*tx;
        *(float2*)&g_z[zb + m0] = make_float2(z0, z1);
        *(float2*)&g_z[zb + m2] = make_float2(z2, z3);
        float s = z0 * (s_maskf[m0]   * (float)(m0   != n))
                + z1 * (s_maskf[m0+1] * (float)(m0+1 != n))
                + z2 * (s_maskf[m2]   * (float)(m2   != n))
                + z3 * (s_maskf[m2+1] * (float)(m2+1 != n));
        float zm = fmaxf(fmaxf(fabsf(z0), fabsf(z1)), fmaxf(fabsf(z2), fabsf(z3)));
        #pragma unroll
        for (int off = 16; off > 0; off >>= 1) {
            s += __shfl_xor_sync(0xffffffffu, s, off);
            zm = fmaxf(zm, __shfl_xor_sync(0xffffffffu, zm, off));
        }
        if (tx == 0) {
            int r = wy*4 + i;
            int mn = g_mask[base_row + n];
            float cm1 = (float)(cnt - 1);
            float denom = fmaxf(cm1, 1.0f);
            su.e.alpha[r] = mn ? (s / denom) : 0.0f;
            su.e.rho[r]   = mn ? (cm1 / denom) : 0.0f;
            su.e.zmax[r]  = fmaxf(zm, 1e-20f);
        }
    }
    if (tid < 64) {
        su.e.ws2[tid] = dup2(w_self[tid]);
        su.e.w2d[tid] = dup2(0.5f * w_out[tid]);
    }
    __syncthreads();

    // a_d per row
    #pragma unroll
    for (int l = 0; l < 8; l++) {
        int idx = tid + l*128;
        int row = idx >> 6, d = idx & 63;
        su.e.a[row][d] = fmaf(su.e.alpha[row], g_u[d],
                              fmaf(su.e.rho[row], g_v[d], b_self[d]));
    }
    __syncthreads();

    // nodal sums: thread = (row, node-pair), full sum over d in-thread
    int be_base = (b*NE + e)*NMAX + row0;
    if (tid < 112) {
        int row = tid / 7;
        int np  = tid - row*7;
        float zmaxr = su.e.zmax[row];
        float znl = zmaxr * g_cheb[2*np];
        float znh = zmaxr * g_cheb[2*np+1];
        ull zn; PACK2(zn, znl, znh);
        const ull k0 = dup2(C0), k1 = dup2(C1), k2 = dup2(C2);
        const ull k3 = dup2(C3), k4 = dup2(C4), k5 = dup2(C5);
        ull acc2 = 0ull;
        float tmax = 0.f;
        #pragma unroll 8
        for (int d = 0; d < 64; d++) {
            ull ad = dup2(su.e.a[row][d]);
            ull xx, tt, p;
            FMA2(xx, su.e.ws2[d], zn, ad);
            MUL2(tt, xx, xx);
            p = k5;
            FMA2(p, p, tt, k4);
            FMA2(p, p, tt, k3);
            FMA2(p, p, tt, k2);
            FMA2(p, p, tt, k1);
            FMA2(p, p, tt, k0);
            ull h;
            FMA2(h, tt, p, xx);             // h = xx*(1+erf(xx/sqrt2))
            FMA2(acc2, su.e.w2d[d], h, acc2);
            tmax = fmaxf(tmax, fmaxf(lo2(tt), hi2(tt)));
        }
        if (tmax > 2.25f) {                 // rare exact fallback at these nodes
            float al = 0.f, ah = 0.f;
            for (int d = 0; d < 64; d++) {
                float a = su.e.a[row][d];
                float ws = lo2(su.e.ws2[d]);
                float w2 = lo2(su.e.w2d[d]);
                float x0 = fmaf(ws, znl, a), x1 = fmaf(ws, znh, a);
                al = fmaf(w2, x0*(1.f + erff(x0*0.7071067811865476f)), al);
                ah = fmaf(w2, x1*(1.f + erff(x1*0.7071067811865476f)), ah);
            }
            PACK2(acc2, al, ah);
        }
        su.e.nod[row][2*np]   = lo2(acc2);
        su.e.nod[row][2*np+1] = hi2(acc2);
    }
    if (tid < 16)
        g_ck[(be_base + tid)*16 + 14] = 1.0f / su.e.zmax[tid];
    __syncthreads();

    // DCT: nodal values -> Chebyshev coefficients
    #pragma unroll
    for (int idx = tid; idx < 224; idx += 128) {
        int row = idx / 14, k = idx - row*14;
        float c = 0.f;
        #pragma unroll
        for (int j = 0; j < 14; j++)
            c = fmaf(__ldg(&g_dct[k*14 + j]), su.e.nod[row][j], c);
        g_ck[(be_base + row)*16 + k] = c;
    }
}

// ---------------------------------------------------------------------------
// K3: pure streaming Clenshaw. Warp per row, lane = 2 packed column pairs.
// ---------------------------------------------------------------------------
__global__ void __launch_bounds__(256) k_main(
        const float* __restrict__ b_out,
        float* __restrict__ out_e, float* __restrict__ out_edge) {
    __shared__ float s_ck[8][16];
    __shared__ float s_mkf[NMAX];
    int t = threadIdx.x;
    int e = blockIdx.y, b = blockIdx.z;
    int rowbase = blockIdx.x * 8;
    int be_base = (b*NE + e)*NMAX + rowbase;
    if (t < 128) ((float*)s_ck)[t] = g_ck[be_base*16 + t];
    else s_mkf[t-128] = (float)g_mask[b*NMAX + (t-128)];
    __syncthreads();

    int lane = t & 31, w = t >> 5;
    int n = rowbase + w;
    long rowz = (long)(be_base + w) * NMAX;
    ull ck[14];
    #pragma unroll
    for (int k = 0; k < 14; k++) ck[k] = dup2(s_ck[w][k]);
    ull rinv2 = dup2(s_ck[w][14]);
    float bo = b_out[0];

    ull za = *(const ull*)&g_z[rowz + 2*lane];
    ull zb = *(const ull*)&g_z[rowz + 64 + 2*lane];
    ull sa, sb, sax, sbx;
    MUL2(sa, za, rinv2);
    MUL2(sb, zb, rinv2);
    ADD2(sax, sa, sa);
    ADD2(sbx, sb, sb);
    ull b1a = 0ull, b2a = 0ull, b1b = 0ull, b2b = 0ull;
    ull negone = dup2(-1.0f);
    #pragma unroll
    for (int k = 13; k >= 1; k--) {
        ull na, nb;
        FMA2(na, sax, b1a, ck[k]);
        FMA2(na, b2a, negone, na);
        FMA2(nb, sbx, b1b, ck[k]);
        FMA2(nb, b2b, negone, nb);
        b2a = b1a; b1a = na;
        b2b = b1b; b1b = nb;
    }
    ull fa, fb;
    FMA2(fa, sa, b1a, ck[0]);
    FMA2(fa, b2a, negone, fa);
    FMA2(fb, sb, b1b, ck[0]);
    FMA2(fb, b2b, negone, fb);

    int m0 = 2*lane, m2 = 64 + 2*lane;
    out_e[((long)(b*NMAX + m0  )*NMAX + n)*NE + e] = lo2(fa) + bo;
    out_e[((long)(b*NMAX + m0+1)*NMAX + n)*NE + e] = hi2(fa) + bo;
    out_e[((long)(b*NMAX + m2  )*NMAX + n)*NE + e] = lo2(fb) + bo;
    out_e[((long)(b*NMAX + m2+1)*NMAX + n)*NE + e] = hi2(fb) + bo;
    if (e == 0) {
        float mkn = s_mkf[n];
        float2 v;
        v = make_float2(mkn*s_mkf[m0]*(float)(n != m0), mkn*s_mkf[m0+1]*(float)(n != m0+1));
        *(float2*)&out_edge[(b*NMAX + n)*NMAX + m0] = v;
        v = make_float2(mkn*s_mkf[m2]*(float)(n != m2), mkn*s_mkf[m2+1]*(float)(n != m2+1));
        *(float2*)&out_edge[(b*NMAX + n)*NMAX + m2] = v;
    }
}

extern "C" void kernel_launch(void* const* d_in, const int* in_sizes, int n_in,
                              void* d_out, int out_size) {
    const float* x      = (const float*)d_in[0];
    const int*   batch  = (const int*)  d_in[1];
    const float* q      = (const float*)d_in[2];
    const float* w_attn = (const float*)d_in[3];
    const float* b_attn = (const float*)d_in[4];
    const float* w_node = (const float*)d_in[5];
    const float* b_node = (const float*)d_in[6];
    const float* w_phi  = (const float*)d_in[7];
    const float* b_phi  = (const float*)d_in[8];
    const float* w_ctx  = (const float*)d_in[9];
    const float* w_self = (const float*)d_in[10];
    const float* b_self = (const float*)d_in[11];
    const float* w_out  = (const float*)d_in[12];
    const float* b_out  = (const float*)d_in[13];
    float* out = (float*)d_out;

    k_setup<<<1, 1024>>>(batch, q, w_phi, b_phi, w_ctx, out + OFF_MASK);
    k_projx<<<dim3(21, 16), 256>>>(x, w_attn, b_attn, w_node, b_node, out + OFF_XHAT);
    k_zrows<<<dim3(8, NE, BATCHES), 128>>>(w_self, b_self, w_out);
    k_main<<<dim3(16, NE, BATCHES), 256>>>(b_out, out + OFF_EHAT, out + OFF_EDGE);
}

// round 8
// speedup vs baseline: 1.2682x; 1.0113x over previous
#include <cuda_runtime.h>
#include <math.h>

#define BATCHES 8
#define NMAX    128
#define PE      64
#define NE      5
#define DS      64
#define NF      8
#define TOTAL   (BATCHES*NMAX)
#define PROJC   (4*NE*PE)
#define NROWS   (BATCHES*NE*NMAX)

#define OFF_EHAT 0
#define OFF_XHAT (BATCHES*NMAX*NMAX*NE)
#define OFF_EDGE (OFF_XHAT + TOTAL*NF)
#define OFF_MASK (OFF_EDGE + BATCHES*NMAX*NMAX)

typedef unsigned long long ull;

__device__ float  g_proj[TOTAL*PROJC];
__device__ int    g_node[BATCHES*NMAX];
__device__ int    g_mask[BATCHES*NMAX];
__device__ int    g_cnt[BATCHES];
__device__ float  g_coef[BATCHES];
__device__ float  g_u[DS];
__device__ float  g_v[DS];
__device__ float  g_dct[14*14];
__device__ float  g_cheb[14];

#define FMA2(d,a,b,c) asm("fma.rn.f32x2 %0, %1, %2, %3;" : "=l"(d) : "l"(a), "l"(b), "l"(c))
#define MUL2(d,a,b)   asm("mul.rn.f32x2 %0, %1, %2;" : "=l"(d) : "l"(a), "l"(b))
#define ADD2(d,a,b)   asm("add.rn.f32x2 %0, %1, %2;" : "=l"(d) : "l"(a), "l"(b))
#define PACK2(d,lo,hi) asm("mov.b64 %0, {%1, %2};" : "=l"(d) : "r"(__float_as_uint(lo)), "r"(__float_as_uint(hi)))

__device__ __forceinline__ ull dup2(float v) { ull d; PACK2(d, v, v); return d; }
__device__ __forceinline__ float lo2(ull v) { return __uint_as_float((unsigned int)v); }
__device__ __forceinline__ float hi2(ull v) { return __uint_as_float((unsigned int)(v >> 32)); }

// erf(x/sqrt(2)) = x * (C0 + C1 x^2 + ... + C5 x^10), |x|<=1.5
#define C0  0.7978845608028654f
#define C1 (-0.13298076013381092f)
#define C2  0.019947114020071635f
#define C3 (-0.0023746564309608790f)
#define C4  2.3087512708529163e-4f
#define C5 (-1.8888357703977833e-5f)
#define PI_F 3.14159265358979323846f

// ---------------------------------------------------------------------------
// K0: dense map, counts, coef, u/v, Chebyshev tables, mask output.
// ---------------------------------------------------------------------------
__global__ void k_setup(const int* __restrict__ batch, const float* __restrict__ q,
                        const float* __restrict__ w_phi, const float* __restrict__ b_phi,
                        const float* __restrict__ w_ctx,
                        float* __restrict__ out_mask) {
    __shared__ int s_start[BATCHES];
    __shared__ int s_cnt[BATCHES];
    int t = threadIdx.x;
    if (t < BATCHES) { s_cnt[t] = 0; s_start[t] = 0; }
    g_node[t] = -1;
    g_mask[t] = 0;
    out_mask[t] = 0.0f;
    if (t < 196) {
        int k = t / 14, j = t % 14;
        float th = (float)(2*j + 1) * (PI_F / 28.0f);
        float sk = (k == 0) ? (1.0f/14.0f) : (2.0f/14.0f);
        g_dct[t] = sk * cosf((float)k * th);
        if (k == 0) g_cheb[j] = cosf(th);
    }
    __syncthreads();
    int b = batch[t];
    if (t == 0 || batch[t-1] != b) s_start[b] = t;
    atomicAdd(&s_cnt[b], 1);
    if (t < DS) {
        float u = 0.f, v = 0.f;
        #pragma unroll 8
        for (int k = 0; k < DS; k++) {
            float wc = w_ctx[k*DS + t];
            u = fmaf(w_phi[k], wc, u);
            v = fmaf(b_phi[k], wc, v);
        }
        g_u[t] = u; g_v[t] = v;
    }
    __syncthreads();
    int pos = t - s_start[b];
    int di = b*NMAX + pos;
    g_node[di] = t;
    g_mask[di] = 1;
    out_mask[di] = 1.0f;
    if (t < BATCHES) {
        g_cnt[t] = s_cnt[t];
        float qq = q[t];
        float c = cosf(6.283185307179586f*qq);
        float s = sinf(6.283185307179586f*qq);
        g_coef[t] = (2.0f - c) / s;
    }
}

// ---------------------------------------------------------------------------
// K1: proj = x @ w_attn + b_attn (dense layout, packed f32x2) + x_hat.
// ---------------------------------------------------------------------------
__global__ void k_projx(const float* __restrict__ x, const float* __restrict__ w,
                        const float* __restrict__ bias,
                        const float* __restrict__ w_node, const float* __restrict__ b_node,
                        float* __restrict__ out_xhat) {
    if (blockIdx.x == 20) {
        int base = blockIdx.y * 512;
        #pragma unroll
        for (int l = 0; l < 2; l++) {
            int id = base + threadIdx.x + l*256;
            int node = id / NF, f = id % NF;
            float acc = 0.f;
            #pragma unroll 8
            for (int k = 0; k < PE; k++)
                acc = fmaf(__ldg(&x[node*PE + k]), __ldg(&w_node[k*NF + f]), acc);
            out_xhat[id] = acc + b_node[f];
        }
        return;
    }
    __shared__ ull Ad[64][64];
    __shared__ ull Wp[64][32];
    int tid = threadIdx.x;
    int tx = tid & 15, ty = tid >> 4;
    int row0 = blockIdx.y * 64;
    int col0 = blockIdx.x * 64;
    #pragma unroll
    for (int l = 0; l < 4; l++) {
        int e = tid + l*256;
        int r = e >> 4, kq = (e & 15) * 4;
        int node = g_node[row0 + r];
        float4 v = make_float4(0.f,0.f,0.f,0.f);
        if (node >= 0) v = *(const float4*)&x[node*PE + kq];
        Ad[r][kq+0] = dup2(v.x);
        Ad[r][kq+1] = dup2(v.y);
        Ad[r][kq+2] = dup2(v.z);
        Ad[r][kq+3] = dup2(v.w);
    }
    #pragma unroll
    for (int l = 0; l < 4; l++) {
        int e = tid + l*256;
        int k = e >> 4, cq = (e & 15) * 4;
        float4 v = *(const float4*)&w[k*PROJC + col0 + cq];
        ull p0, p1;
        PACK2(p0, v.x, v.y);
        PACK2(p1, v.z, v.w);
        Wp[k][cq/2]   = p0;
        Wp[k][cq/2+1] = p1;
    }
    __syncthreads();
    ull acc[4][2];
    #pragma unroll
    for (int i = 0; i < 4; i++) { acc[i][0] = 0ull; acc[i][1] = 0ull; }
    #pragma unroll 4
    for (int kk = 0; kk < 64; kk += 2) {
        ulonglong2 ai[4];
        #pragma unroll
        for (int i = 0; i < 4; i++)
            ai[i] = *(const ulonglong2*)&Ad[ty + 16*i][kk];
        ull b00 = Wp[kk][tx],   b10 = Wp[kk][tx+16];
        ull b01 = Wp[kk+1][tx], b11 = Wp[kk+1][tx+16];
        #pragma unroll
        for (int i = 0; i < 4; i++) {
            FMA2(acc[i][0], ai[i].x, b00, acc[i][0]);
            FMA2(acc[i][0], ai[i].y, b01, acc[i][0]);
            FMA2(acc[i][1], ai[i].x, b10, acc[i][1]);
            FMA2(acc[i][1], ai[i].y, b11, acc[i][1]);
        }
    }
    #pragma unroll
    for (int i = 0; i < 4; i++) {
        int r = row0 + ty + 16*i;
        int node = g_node[r];
        #pragma unroll
        for (int j = 0; j < 2; j++) {
            int cp = tx + 16*j;
            int c = col0 + 2*cp;
            float v0 = 0.f, v1 = 0.f;
            if (node >= 0) {
                v0 = lo2(acc[i][j]) + bias[c];
                v1 = hi2(acc[i][j]) + bias[c+1];
            }
            *(float2*)&g_proj[r*PROJC + c] = make_float2(v0, v1);
        }
    }
}

// ---------------------------------------------------------------------------
// K2 (fused): z GEMM -> row stats -> Chebyshev coefficients -> in-register
// Clenshaw -> out_e. z never leaves registers; no k_main kernel.
// ---------------------------------------------------------------------------
struct SmemGemm { ull Kd[64][17]; float Qt[64][130]; };
struct SmemEpi  {
    float a[16][64];            // per-row gelu offsets a_d
    float nod[16][16];          // nodal sums (14 used)
    ull   ck[16][14];           // duplicated Chebyshev coeffs per row
    ull   ws2[64];              // dup2(w_self)
    ull   w2d[64];              // dup2(0.5*w_out)
    float alpha[16], rho[16], zmax[16], rinv[16];
};

__global__ void __launch_bounds__(128) k_zmain(
        const float* __restrict__ w_self, const float* __restrict__ b_self,
        const float* __restrict__ w_out, const float* __restrict__ b_out,
        float* __restrict__ out_e, float* __restrict__ out_edge) {
    __shared__ union { SmemGemm g; SmemEpi e; } su;
    __shared__ float s_maskf[NMAX];
    const float scale = 0.05590169943749474f;   // 1/sqrt(320)
    int tid = threadIdx.x;
    int tx = tid & 31, wy = tid >> 5;
    int tile = blockIdx.x, e = blockIdx.y, b = blockIdx.z;
    int row0 = tile * 16;
    int base_row = b * NMAX;
    float coef = g_coef[b];
    s_maskf[tid] = (float)g_mask[base_row + tid];

    ull acc[4][2];
    #pragma unroll
    for (int i = 0; i < 4; i++) { acc[i][0] = 0ull; acc[i][1] = 0ull; }

    // ---- Phase A: GEMM ----
    #pragma unroll
    for (int p = 0; p < 2; p++) {
        float cs = p ? coef : 1.0f;
        int koff = (p ? 2*NE*PE : 0) + e*PE;
        int qoff = (p ? 3*NE*PE : NE*PE) + e*PE;
        if (p) __syncthreads();
        #pragma unroll
        for (int l = 0; l < 2; l++) {
            int e4 = tid + l*128;
            int r = e4 >> 4;
            int kq = (e4 & 15) * 4;
            int sw = (kq >> 4) & 3;
            float4 v = *(const float4*)&g_proj[(base_row + row0 + r)*PROJC + koff + kq];
            su.g.Kd[kq+0][r ^ sw] = dup2(v.x * cs);
            su.g.Kd[kq+1][r ^ sw] = dup2(v.y * cs);
            su.g.Kd[kq+2][r ^ sw] = dup2(v.z * cs);
            su.g.Kd[kq+3][r ^ sw] = dup2(v.w * cs);
        }
        #pragma unroll
        for (int l = 0; l < 16; l++) {
            int e4 = tid + l*128;
            int m = e4 >> 4;
            int kq = (e4 & 15) * 4;
            int ms = m ^ (((kq >> 4) & 3) << 1);
            float4 v = *(const float4*)&g_proj[(base_row + m)*PROJC + qoff + kq];
            su.g.Qt[kq+0][ms] = v.x;
            su.g.Qt[kq+1][ms] = v.y;
            su.g.Qt[kq+2][ms] = v.z;
            su.g.Qt[kq+3][ms] = v.w;
        }
        __syncthreads();
        #pragma unroll
        for (int kg = 0; kg < 4; kg++) {
            int c0 = (2*tx) ^ (kg << 1);
            int r0s = (4*wy + 0) ^ kg;
            int r1s = (4*wy + 1) ^ kg;
            int r2s = (4*wy + 2) ^ kg;
            int r3s = (4*wy + 3) ^ kg;
            #pragma unroll
            for (int kk = 0; kk < 16; kk++) {
                int k = kg*16 + kk;
                ull b0 = *(const ull*)&su.g.Qt[k][c0];
                ull b1 = *(const ull*)&su.g.Qt[k][c0 + 64];
                ull a0 = su.g.Kd[k][r0s], a1 = su.g.Kd[k][r1s];
                ull a2 = su.g.Kd[k][r2s], a3 = su.g.Kd[k][r3s];
                FMA2(acc[0][0], a0, b0, acc[0][0]);
                FMA2(acc[0][1], a0, b1, acc[0][1]);
                FMA2(acc[1][0], a1, b0, acc[1][0]);
                FMA2(acc[1][1], a1, b1, acc[1][1]);
                FMA2(acc[2][0], a2, b0, acc[2][0]);
                FMA2(acc[2][1], a2, b1, acc[2][1]);
                FMA2(acc[3][0], a3, b0, acc[3][0]);
                FMA2(acc[3][1], a3, b1, acc[3][1]);
            }
        }
    }
    __syncthreads();    // GEMM tiles dead; epilogue aliases su

    // ---- Phase B: scale z (stays in registers), row sums / zmax ----
    ull sc2 = dup2(scale);
    int cnt = g_cnt[b];
    #pragma unroll
    for (int i = 0; i < 4; i++) {
        MUL2(acc[i][0], acc[i][0], sc2);
        MUL2(acc[i][1], acc[i][1], sc2);
        int n = row0 + wy*4 + i;
        float z0 = lo2(acc[i][0]), z1 = hi2(acc[i][0]);
        float z2 = lo2(acc[i][1]), z3 = hi2(acc[i][1]);
        int m0 = 2*tx, m2 = 64 + 2*tx;
        float s = z0 * (s_maskf[m0]   * (float)(m0   != n))
                + z1 * (s_maskf[m0+1] * (float)(m0+1 != n))
                + z2 * (s_maskf[m2]   * (float)(m2   != n))
                + z3 * (s_maskf[m2+1] * (float)(m2+1 != n));
        float zm = fmaxf(fmaxf(fabsf(z0), fabsf(z1)), fmaxf(fabsf(z2), fabsf(z3)));
        #pragma unroll
        for (int off = 16; off > 0; off >>= 1) {
            s += __shfl_xor_sync(0xffffffffu, s, off);
            zm = fmaxf(zm, __shfl_xor_sync(0xffffffffu, zm, off));
        }
        if (tx == 0) {
            int r = wy*4 + i;
            int mn = g_mask[base_row + n];
            float cm1 = (float)(cnt - 1);
            float denom = fmaxf(cm1, 1.0f);
            su.e.alpha[r] = mn ? (s / denom) : 0.0f;
            su.e.rho[r]   = mn ? (cm1 / denom) : 0.0f;
            float zmx = fmaxf(zm, 1e-20f);
            su.e.zmax[r]  = zmx;
            su.e.rinv[r]  = 1.0f / zmx;
        }
    }
    if (tid < 64) {
        su.e.ws2[tid] = dup2(w_self[tid]);
        su.e.w2d[tid] = dup2(0.5f * w_out[tid]);
    }
    __syncthreads();

    // ---- Phase C1: per-row gelu offsets ----
    #pragma unroll
    for (int l = 0; l < 8; l++) {
        int idx = tid + l*128;
        int row = idx >> 6, d = idx & 63;
        su.e.a[row][d] = fmaf(su.e.alpha[row], g_u[d],
                              fmaf(su.e.rho[row], g_v[d], b_self[d]));
    }
    __syncthreads();

    // ---- Phase C2: nodal sums (thread = row x node-pair, in-thread over d) ----
    if (tid < 112) {
        int row = tid / 7;
        int np  = tid - row*7;
        float zmaxr = su.e.zmax[row];
        float znl = zmaxr * g_cheb[2*np];
        float znh = zmaxr * g_cheb[2*np+1];
        ull zn; PACK2(zn, znl, znh);
        const ull k0 = dup2(C0), k1 = dup2(C1), k2 = dup2(C2);
        const ull k3 = dup2(C3), k4 = dup2(C4), k5 = dup2(C5);
        ull acc2 = 0ull;
        float tmax = 0.f;
        #pragma unroll 8
        for (int d = 0; d < 64; d++) {
            ull ad = dup2(su.e.a[row][d]);
            ull xx, tt, p;
            FMA2(xx, su.e.ws2[d], zn, ad);
            MUL2(tt, xx, xx);
            p = k5;
            FMA2(p, p, tt, k4);
            FMA2(p, p, tt, k3);
            FMA2(p, p, tt, k2);
            FMA2(p, p, tt, k1);
            FMA2(p, p, tt, k0);
            ull h;
            FMA2(h, tt, p, xx);             // h = xx*(1+erf(xx/sqrt2))
            FMA2(acc2, su.e.w2d[d], h, acc2);
            tmax = fmaxf(tmax, fmaxf(lo2(tt), hi2(tt)));
        }
        if (tmax > 2.25f) {                 // rare exact fallback at these nodes
            float al = 0.f, ah = 0.f;
            for (int d = 0; d < 64; d++) {
                float a = su.e.a[row][d];
                float ws = lo2(su.e.ws2[d]);
                float w2 = lo2(su.e.w2d[d]);
                float x0 = fmaf(ws, znl, a), x1 = fmaf(ws, znh, a);
                al = fmaf(w2, x0*(1.f + erff(x0*0.7071067811865476f)), al);
                ah = fmaf(w2, x1*(1.f + erff(x1*0.7071067811865476f)), ah);
            }
            PACK2(acc2, al, ah);
        }
        su.e.nod[row][2*np]   = lo2(acc2);
        su.e.nod[row][2*np+1] = hi2(acc2);
    }
    __syncthreads();

    // ---- Phase C3: DCT -> Chebyshev coefficients (b_out folded into c0) ----
    float bo = b_out[0];
    #pragma unroll
    for (int idx = tid; idx < 224; idx += 128) {
        int row = idx / 14, k = idx - row*14;
        float c = 0.f;
        #pragma unroll
        for (int j = 0; j < 14; j++)
            c = fmaf(__ldg(&g_dct[k*14 + j]), su.e.nod[row][j], c);
        if (k == 0) c += bo;
        su.e.ck[row][k] = dup2(c);
    }
    __syncthreads();

    // ---- Phase D: in-register Clenshaw + stores ----
    ull negone = dup2(-1.0f);
    #pragma unroll
    for (int i = 0; i < 4; i++) {
        int row = wy*4 + i;
        int n = row0 + row;
        ull rinv2 = dup2(su.e.rinv[row]);
        ull sa, sb, sax, sbx;
        MUL2(sa, acc[i][0], rinv2);
        MUL2(sb, acc[i][1], rinv2);
        ADD2(sax, sa, sa);
        ADD2(sbx, sb, sb);
        ull b1a = 0ull, b2a = 0ull, b1b = 0ull, b2b = 0ull;
        #pragma unroll
        for (int k = 13; k >= 1; k--) {
            ull ckk = su.e.ck[row][k];
            ull na, nb;
            FMA2(na, sax, b1a, ckk);
            FMA2(na, b2a, negone, na);
            FMA2(nb, sbx, b1b, ckk);
            FMA2(nb, b2b, negone, nb);
            b2a = b1a; b1a = na;
            b2b = b1b; b1b = nb;
        }
        ull ck0 = su.e.ck[row][0];
        ull fa, fb;
        FMA2(fa, sa, b1a, ck0);
        FMA2(fa, b2a, negone, fa);
        FMA2(fb, sb, b1b, ck0);
        FMA2(fb, b2b, negone, fb);
        int m0 = 2*tx, m2 = 64 + 2*tx;
        out_e[((long)(b*NMAX + m0  )*NMAX + n)*NE + e] = lo2(fa);
        out_e[((long)(b*NMAX + m0+1)*NMAX + n)*NE + e] = hi2(fa);
        out_e[((long)(b*NMAX + m2  )*NMAX + n)*NE + e] = lo2(fb);
        out_e[((long)(b*NMAX + m2+1)*NMAX + n)*NE + e] = hi2(fb);
    }
    if (e == 0) {
        #pragma unroll
        for (int i = 0; i < 4; i++) {
            int n = row0 + wy*4 + i;
            float mkn = s_maskf[n];
            int m0 = 2*tx, m2 = 64 + 2*tx;
            float2 v;
            v = make_float2(mkn*s_maskf[m0]*(float)(n != m0),
                            mkn*s_maskf[m0+1]*(float)(n != m0+1));
            *(float2*)&out_edge[(b*NMAX + n)*NMAX + m0] = v;
            v = make_float2(mkn*s_maskf[m2]*(float)(n != m2),
                            mkn*s_maskf[m2+1]*(float)(n != m2+1));
            *(float2*)&out_edge[(b*NMAX + n)*NMAX + m2] = v;
        }
    }
}

extern "C" void kernel_launch(void* const* d_in, const int* in_sizes, int n_in,
                              void* d_out, int out_size) {
    const float* x      = (const float*)d_in[0];
    const int*   batch  = (const int*)  d_in[1];
    const float* q      = (const float*)d_in[2];
    const float* w_attn = (const float*)d_in[3];
    const float* b_attn = (const float*)d_in[4];
    const float* w_node = (const float*)d_in[5];
    const float* b_node = (const float*)d_in[6];
    const float* w_phi  = (const float*)d_in[7];
    const float* b_phi  = (const float*)d_in[8];
    const float* w_ctx  = (const float*)d_in[9];
    const float* w_self = (const float*)d_in[10];
    const float* b_self = (const float*)d_in[11];
    const float* w_out  = (const float*)d_in[12];
    const float* b_out  = (const float*)d_in[13];
    float* out = (float*)d_out;

    k_setup<<<1, 1024>>>(batch, q, w_phi, b_phi, w_ctx, out + OFF_MASK);
    k_projx<<<dim3(21, 16), 256>>>(x, w_attn, b_attn, w_node, b_node, out + OFF_XHAT);
    k_zmain<<<dim3(8, NE, BATCHES), 128>>>(w_self, b_self, w_out, b_out,
                                           out + OFF_EHAT, out + OFF_EDGE);
}

// round 9
// speedup vs baseline: 1.5290x; 1.2056x over previous
#include <cuda_runtime.h>
#include <math.h>

#define BATCHES 8
#define NMAX    128
#define PE      64
#define NE      5
#define DS      64
#define NF      8
#define TOTAL   (BATCHES*NMAX)
#define PROJC   (4*NE*PE)

#define OFF_EHAT 0
#define OFF_XHAT (BATCHES*NMAX*NMAX*NE)
#define OFF_EDGE (OFF_XHAT + TOTAL*NF)
#define OFF_MASK (OFF_EDGE + BATCHES*NMAX*NMAX)

typedef unsigned long long ull;

__device__ float  g_proj[TOTAL*PROJC];
__device__ int    g_cnt[BATCHES];
__device__ float  g_coef[BATCHES];
__device__ float  g_u[DS];
__device__ float  g_v[DS];
__device__ float  g_dct[14*14];
__device__ float  g_cheb[14];

#define FMA2(d,a,b,c) asm("fma.rn.f32x2 %0, %1, %2, %3;" : "=l"(d) : "l"(a), "l"(b), "l"(c))
#define MUL2(d,a,b)   asm("mul.rn.f32x2 %0, %1, %2;" : "=l"(d) : "l"(a), "l"(b))
#define ADD2(d,a,b)   asm("add.rn.f32x2 %0, %1, %2;" : "=l"(d) : "l"(a), "l"(b))
#define PACK2(d,lo,hi) asm("mov.b64 %0, {%1, %2};" : "=l"(d) : "r"(__float_as_uint(lo)), "r"(__float_as_uint(hi)))

__device__ __forceinline__ ull dup2(float v) { ull d; PACK2(d, v, v); return d; }
__device__ __forceinline__ float lo2(ull v) { return __uint_as_float((unsigned int)v); }
__device__ __forceinline__ float hi2(ull v) { return __uint_as_float((unsigned int)(v >> 32)); }

__device__ __forceinline__ int lbound(const int* __restrict__ a, int n, int v) {
    int lo = 0, hi = n;
    while (lo < hi) {
        int m = (lo + hi) >> 1;
        if (a[m] < v) lo = m + 1; else hi = m;
    }
    return lo;
}

// erf(x/sqrt(2)) = x * (C0 + C1 x^2 + ... + C5 x^10), |x|<=1.5
#define C0  0.7978845608028654f
#define C1 (-0.13298076013381092f)
#define C2  0.019947114020071635f
#define C3 (-0.0023746564309608790f)
#define C4  2.3087512708529163e-4f
#define C5 (-1.8888357703977833e-5f)
#define PI_F 3.14159265358979323846f

// ---------------------------------------------------------------------------
// K1: proj GEMM (dense layout via inline binary search) + x_hat (bx==20)
//     + prep block (bx==21): u/v, DCT tables, cnt/coef, out_mask.
// ---------------------------------------------------------------------------
struct PSmemGemm { ull Ad[64][64]; ull Wp[64][32]; };
struct PSmemPrep { float ru[4][64]; float rv[4][64]; int start[12]; };

__global__ void __launch_bounds__(256) k_projx(
        const float* __restrict__ x, const float* __restrict__ w,
        const float* __restrict__ bias,
        const float* __restrict__ w_node, const float* __restrict__ b_node,
        const int* __restrict__ batch, const float* __restrict__ q,
        const float* __restrict__ w_phi, const float* __restrict__ b_phi,
        const float* __restrict__ w_ctx,
        float* __restrict__ out_xhat, float* __restrict__ out_mask) {
    __shared__ union { PSmemGemm g; PSmemPrep p; } su;
    int tid = threadIdx.x;
    if (blockIdx.x == 20) {             // x_hat
        int base = blockIdx.y * 512;
        #pragma unroll
        for (int l = 0; l < 2; l++) {
            int id = base + tid + l*256;
            int node = id / NF, f = id % NF;
            float acc = 0.f;
            #pragma unroll 8
            for (int k = 0; k < PE; k++)
                acc = fmaf(__ldg(&x[node*PE + k]), __ldg(&w_node[k*NF + f]), acc);
            out_xhat[id] = acc + b_node[f];
        }
        return;
    }
    if (blockIdx.x == 21) {             // prep
        if (blockIdx.y) return;
        if (tid < 9) su.p.start[tid] = lbound(batch, TOTAL, tid);
        if (tid < 196) {
            int k = tid / 14, j = tid % 14;
            float th = (float)(2*j + 1) * (PI_F / 28.0f);
            float sk = (k == 0) ? (1.0f/14.0f) : (2.0f/14.0f);
            g_dct[tid] = sk * cosf((float)k * th);
            if (k == 0) g_cheb[j] = cosf(th);
        }
        int d = tid & 63, qd = tid >> 6;
        float u = 0.f, v = 0.f;
        #pragma unroll
        for (int k = qd*16; k < qd*16 + 16; k++) {
            float wc = w_ctx[k*DS + d];
            u = fmaf(w_phi[k], wc, u);
            v = fmaf(b_phi[k], wc, v);
        }
        su.p.ru[qd][d] = u;
        su.p.rv[qd][d] = v;
        __syncthreads();
        if (qd == 0) {
            g_u[d] = su.p.ru[0][d] + su.p.ru[1][d] + su.p.ru[2][d] + su.p.ru[3][d];
            g_v[d] = su.p.rv[0][d] + su.p.rv[1][d] + su.p.rv[2][d] + su.p.rv[3][d];
        }
        if (tid < BATCHES) {
            g_cnt[tid] = su.p.start[tid+1] - su.p.start[tid];
            float qq = q[tid];
            float c = cosf(6.283185307179586f*qq);
            float s = sinf(6.283185307179586f*qq);
            g_coef[tid] = (2.0f - c) / s;
        }
        #pragma unroll
        for (int l = 0; l < 4; l++) {
            int idx = tid + l*256;
            int bb = idx >> 7, pos = idx & 127;
            int cnt = su.p.start[bb+1] - su.p.start[bb];
            out_mask[idx] = (pos < cnt) ? 1.0f : 0.0f;
        }
        return;
    }
    // ---- main GEMM blocks ----
    int row0 = blockIdx.y * 64;
    int col0 = blockIdx.x * 64;
    int bb = row0 >> 7;                 // 64-row tile lies in one graph
    int sb_start = lbound(batch, TOTAL, bb);
    int sb_cnt   = lbound(batch, TOTAL, bb+1) - sb_start;
    int tx = tid & 15, ty = tid >> 4;
    #pragma unroll
    for (int l = 0; l < 4; l++) {
        int e = tid + l*256;
        int r = e >> 4, kq = (e & 15) * 4;
        int pos = (row0 + r) & 127;
        float4 v = make_float4(0.f,0.f,0.f,0.f);
        if (pos < sb_cnt) v = *(const float4*)&x[(sb_start + pos)*PE + kq];
        su.g.Ad[r][kq+0] = dup2(v.x);
        su.g.Ad[r][kq+1] = dup2(v.y);
        su.g.Ad[r][kq+2] = dup2(v.z);
        su.g.Ad[r][kq+3] = dup2(v.w);
    }
    #pragma unroll
    for (int l = 0; l < 4; l++) {
        int e = tid + l*256;
        int k = e >> 4, cq = (e & 15) * 4;
        float4 v = *(const float4*)&w[k*PROJC + col0 + cq];
        ull p0, p1;
        PACK2(p0, v.x, v.y);
        PACK2(p1, v.z, v.w);
        su.g.Wp[k][cq/2]   = p0;
        su.g.Wp[k][cq/2+1] = p1;
    }
    __syncthreads();
    ull acc[4][2];
    #pragma unroll
    for (int i = 0; i < 4; i++) { acc[i][0] = 0ull; acc[i][1] = 0ull; }
    #pragma unroll 4
    for (int kk = 0; kk < 64; kk += 2) {
        ulonglong2 ai[4];
        #pragma unroll
        for (int i = 0; i < 4; i++)
            ai[i] = *(const ulonglong2*)&su.g.Ad[ty + 16*i][kk];
        ull b00 = su.g.Wp[kk][tx],   b10 = su.g.Wp[kk][tx+16];
        ull b01 = su.g.Wp[kk+1][tx], b11 = su.g.Wp[kk+1][tx+16];
        #pragma unroll
        for (int i = 0; i < 4; i++) {
            FMA2(acc[i][0], ai[i].x, b00, acc[i][0]);
            FMA2(acc[i][0], ai[i].y, b01, acc[i][0]);
            FMA2(acc[i][1], ai[i].x, b10, acc[i][1]);
            FMA2(acc[i][1], ai[i].y, b11, acc[i][1]);
        }
    }
    #pragma unroll
    for (int i = 0; i < 4; i++) {
        int r = row0 + ty + 16*i;
        int valid = ((r & 127) < sb_cnt);
        #pragma unroll
        for (int j = 0; j < 2; j++) {
            int cp = tx + 16*j;
            int c = col0 + 2*cp;
            float v0 = 0.f, v1 = 0.f;
            if (valid) {
                v0 = lo2(acc[i][j]) + bias[c];
                v1 = hi2(acc[i][j]) + bias[c+1];
            }
            *(float2*)&g_proj[r*PROJC + c] = make_float2(v0, v1);
        }
    }
}

// ---------------------------------------------------------------------------
// K2 (fused): z GEMM -> row stats -> Chebyshev coefficients -> in-register
// Clenshaw -> out_e + edge_mask. Mask derived from g_cnt.
// ---------------------------------------------------------------------------
struct SmemGemm { ull Kd[64][17]; float Qt[64][130]; };
struct SmemEpi  {
    float a[16][64];
    float nod[16][16];
    ull   ck[16][14];
    ull   ws2[64];
    ull   w2d[64];
    float alpha[16], rho[16], zmax[16], rinv[16];
};

__global__ void __launch_bounds__(128) k_zmain(
        const float* __restrict__ w_self, const float* __restrict__ b_self,
        const float* __restrict__ w_out, const float* __restrict__ b_out,
        float* __restrict__ out_e, float* __restrict__ out_edge) {
    __shared__ union { SmemGemm g; SmemEpi e; } su;
    __shared__ float s_maskf[NMAX];
    const float scale = 0.05590169943749474f;   // 1/sqrt(320)
    int tid = threadIdx.x;
    int tx = tid & 31, wy = tid >> 5;
    int tile = blockIdx.x, e = blockIdx.y, b = blockIdx.z;
    int row0 = tile * 16;
    int base_row = b * NMAX;
    int cnt = g_cnt[b];
    float coef = g_coef[b];
    s_maskf[tid] = (tid < cnt) ? 1.0f : 0.0f;

    ull acc[4][2];
    #pragma unroll
    for (int i = 0; i < 4; i++) { acc[i][0] = 0ull; acc[i][1] = 0ull; }

    // ---- Phase A: GEMM ----
    #pragma unroll
    for (int p = 0; p < 2; p++) {
        float cs = p ? coef : 1.0f;
        int koff = (p ? 2*NE*PE : 0) + e*PE;
        int qoff = (p ? 3*NE*PE : NE*PE) + e*PE;
        if (p) __syncthreads();
        #pragma unroll
        for (int l = 0; l < 2; l++) {
            int e4 = tid + l*128;
            int r = e4 >> 4;
            int kq = (e4 & 15) * 4;
            int sw = (kq >> 4) & 3;
            float4 v = *(const float4*)&g_proj[(base_row + row0 + r)*PROJC + koff + kq];
            su.g.Kd[kq+0][r ^ sw] = dup2(v.x * cs);
            su.g.Kd[kq+1][r ^ sw] = dup2(v.y * cs);
            su.g.Kd[kq+2][r ^ sw] = dup2(v.z * cs);
            su.g.Kd[kq+3][r ^ sw] = dup2(v.w * cs);
        }
        #pragma unroll
        for (int l = 0; l < 16; l++) {
            int e4 = tid + l*128;
            int m = e4 >> 4;
            int kq = (e4 & 15) * 4;
            int ms = m ^ (((kq >> 4) & 3) << 1);
            float4 v = *(const float4*)&g_proj[(base_row + m)*PROJC + qoff + kq];
            su.g.Qt[kq+0][ms] = v.x;
            su.g.Qt[kq+1][ms] = v.y;
            su.g.Qt[kq+2][ms] = v.z;
            su.g.Qt[kq+3][ms] = v.w;
        }
        __syncthreads();
        #pragma unroll
        for (int kg = 0; kg < 4; kg++) {
            int c0 = (2*tx) ^ (kg << 1);
            int r0s = (4*wy + 0) ^ kg;
            int r1s = (4*wy + 1) ^ kg;
            int r2s = (4*wy + 2) ^ kg;
            int r3s = (4*wy + 3) ^ kg;
            #pragma unroll
            for (int kk = 0; kk < 16; kk++) {
                int k = kg*16 + kk;
                ull b0 = *(const ull*)&su.g.Qt[k][c0];
                ull b1 = *(const ull*)&su.g.Qt[k][c0 + 64];
                ull a0 = su.g.Kd[k][r0s], a1 = su.g.Kd[k][r1s];
                ull a2 = su.g.Kd[k][r2s], a3 = su.g.Kd[k][r3s];
                FMA2(acc[0][0], a0, b0, acc[0][0]);
                FMA2(acc[0][1], a0, b1, acc[0][1]);
                FMA2(acc[1][0], a1, b0, acc[1][0]);
                FMA2(acc[1][1], a1, b1, acc[1][1]);
                FMA2(acc[2][0], a2, b0, acc[2][0]);
                FMA2(acc[2][1], a2, b1, acc[2][1]);
                FMA2(acc[3][0], a3, b0, acc[3][0]);
                FMA2(acc[3][1], a3, b1, acc[3][1]);
            }
        }
    }
    __syncthreads();    // GEMM tiles dead; epilogue aliases su

    // ---- Phase B: scale z in registers, row sums / zmax ----
    ull sc2 = dup2(scale);
    #pragma unroll
    for (int i = 0; i < 4; i++) {
        MUL2(acc[i][0], acc[i][0], sc2);
        MUL2(acc[i][1], acc[i][1], sc2);
        int n = row0 + wy*4 + i;
        float z0 = lo2(acc[i][0]), z1 = hi2(acc[i][0]);
        float z2 = lo2(acc[i][1]), z3 = hi2(acc[i][1]);
        int m0 = 2*tx, m2 = 64 + 2*tx;
        float s = z0 * (s_maskf[m0]   * (float)(m0   != n))
                + z1 * (s_maskf[m0+1] * (float)(m0+1 != n))
                + z2 * (s_maskf[m2]   * (float)(m2   != n))
                + z3 * (s_maskf[m2+1] * (float)(m2+1 != n));
        float zm = fmaxf(fmaxf(fabsf(z0), fabsf(z1)), fmaxf(fabsf(z2), fabsf(z3)));
        #pragma unroll
        for (int off = 16; off > 0; off >>= 1) {
            s += __shfl_xor_sync(0xffffffffu, s, off);
            zm = fmaxf(zm, __shfl_xor_sync(0xffffffffu, zm, off));
        }
        if (tx == 0) {
            int r = wy*4 + i;
            int mn = (n < cnt);
            float cm1 = (float)(cnt - 1);
            float denom = fmaxf(cm1, 1.0f);
            su.e.alpha[r] = mn ? (s / denom) : 0.0f;
            su.e.rho[r]   = mn ? (cm1 / denom) : 0.0f;
            float zmx = fmaxf(zm, 1e-20f);
            su.e.zmax[r]  = zmx;
            su.e.rinv[r]  = 1.0f / zmx;
        }
    }
    if (tid < 64) {
        su.e.ws2[tid] = dup2(w_self[tid]);
        su.e.w2d[tid] = dup2(0.5f * w_out[tid]);
    }
    __syncthreads();

    // ---- Phase C1: per-row gelu offsets ----
    #pragma unroll
    for (int l = 0; l < 8; l++) {
        int idx = tid + l*128;
        int row = idx >> 6, d = idx & 63;
        su.e.a[row][d] = fmaf(su.e.alpha[row], g_u[d],
                              fmaf(su.e.rho[row], g_v[d], b_self[d]));
    }
    __syncthreads();

    // ---- Phase C2: nodal sums (thread = row x node-pair, in-thread over d) ----
    if (tid < 112) {
        int row = tid / 7;
        int np  = tid - row*7;
        float zmaxr = su.e.zmax[row];
        float znl = zmaxr * g_cheb[2*np];
        float znh = zmaxr * g_cheb[2*np+1];
        ull zn; PACK2(zn, znl, znh);
        const ull k0 = dup2(C0), k1 = dup2(C1), k2 = dup2(C2);
        const ull k3 = dup2(C3), k4 = dup2(C4), k5 = dup2(C5);
        ull acc2 = 0ull;
        float tmax = 0.f;
        #pragma unroll 8
        for (int d = 0; d < 64; d++) {
            ull ad = dup2(su.e.a[row][d]);
            ull xx, tt, p;
            FMA2(xx, su.e.ws2[d], zn, ad);
            MUL2(tt, xx, xx);
            p = k5;
            FMA2(p, p, tt, k4);
            FMA2(p, p, tt, k3);
            FMA2(p, p, tt, k2);
            FMA2(p, p, tt, k1);
            FMA2(p, p, tt, k0);
            ull h;
            FMA2(h, tt, p, xx);
            FMA2(acc2, su.e.w2d[d], h, acc2);
            tmax = fmaxf(tmax, fmaxf(lo2(tt), hi2(tt)));
        }
        if (tmax > 2.25f) {
            float al = 0.f, ah = 0.f;
            for (int d = 0; d < 64; d++) {
                float a = su.e.a[row][d];
                float ws = lo2(su.e.ws2[d]);
                float w2 = lo2(su.e.w2d[d]);
                float x0 = fmaf(ws, znl, a), x1 = fmaf(ws, znh, a);
                al = fmaf(w2, x0*(1.f + erff(x0*0.7071067811865476f)), al);
                ah = fmaf(w2, x1*(1.f + erff(x1*0.7071067811865476f)), ah);
            }
            PACK2(acc2, al, ah);
        }
        su.e.nod[row][2*np]   = lo2(acc2);
        su.e.nod[row][2*np+1] = hi2(acc2);
    }
    __syncthreads();

    // ---- Phase C3: DCT -> Chebyshev coefficients (b_out folded into c0) ----
    float bo = b_out[0];
    #pragma unroll
    for (int idx = tid; idx < 224; idx += 128) {
        int row = idx / 14, k = idx - row*14;
        float c = 0.f;
        #pragma unroll
        for (int j = 0; j < 14; j++)
            c = fmaf(__ldg(&g_dct[k*14 + j]), su.e.nod[row][j], c);
        if (k == 0) c += bo;
        su.e.ck[row][k] = dup2(c);
    }
    __syncthreads();

    // ---- Phase D: in-register Clenshaw + stores ----
    ull negone = dup2(-1.0f);
    #pragma unroll
    for (int i = 0; i < 4; i++) {
        int row = wy*4 + i;
        int n = row0 + row;
        ull rinv2 = dup2(su.e.rinv[row]);
        ull sa, sb, sax, sbx;
        MUL2(sa, acc[i][0], rinv2);
        MUL2(sb, acc[i][1], rinv2);
        ADD2(sax, sa, sa);
        ADD2(sbx, sb, sb);
        ull b1a = 0ull, b2a = 0ull, b1b = 0ull, b2b = 0ull;
        #pragma unroll
        for (int k = 13; k >= 1; k--) {
            ull ckk = su.e.ck[row][k];
            ull na, nb;
            FMA2(na, sax, b1a, ckk);
            FMA2(na, b2a, negone, na);
            FMA2(nb, sbx, b1b, ckk);
            FMA2(nb, b2b, negone, nb);
            b2a = b1a; b1a = na;
            b2b = b1b; b1b = nb;
        }
        ull ck0 = su.e.ck[row][0];
        ull fa, fb;
        FMA2(fa, sa, b1a, ck0);
        FMA2(fa, b2a, negone, fa);
        FMA2(fb, sb, b1b, ck0);
        FMA2(fb, b2b, negone, fb);
        int m0 = 2*tx, m2 = 64 + 2*tx;
        out_e[((long)(b*NMAX + m0  )*NMAX + n)*NE + e] = lo2(fa);
        out_e[((long)(b*NMAX + m0+1)*NMAX + n)*NE + e] = hi2(fa);
        out_e[((long)(b*NMAX + m2  )*NMAX + n)*NE + e] = lo2(fb);
        out_e[((long)(b*NMAX + m2+1)*NMAX + n)*NE + e] = hi2(fb);
    }
    if (e == 0) {
        #pragma unroll
        for (int i = 0; i < 4; i++) {
            int n = row0 + wy*4 + i;
            float mkn = s_maskf[n];
            int m0 = 2*tx, m2 = 64 + 2*tx;
            float2 v;
            v = make_float2(mkn*s_maskf[m0]*(float)(n != m0),
                            mkn*s_maskf[m0+1]*(float)(n != m0+1));
            *(float2*)&out_edge[(b*NMAX + n)*NMAX + m0] = v;
            v = make_float2(mkn*s_maskf[m2]*(float)(n != m2),
                            mkn*s_maskf[m2+1]*(float)(n != m2+1));
            *(float2*)&out_edge[(b*NMAX + n)*NMAX + m2] = v;
        }
    }
}

extern "C" void kernel_launch(void* const* d_in, const int* in_sizes, int n_in,
                              void* d_out, int out_size) {
    const float* x      = (const float*)d_in[0];
    const int*   batch  = (const int*)  d_in[1];
    const float* q      = (const float*)d_in[2];
    const float* w_attn = (const float*)d_in[3];
    const float* b_attn = (const float*)d_in[4];
    const float* w_node = (const float*)d_in[5];
    const float* b_node = (const float*)d_in[6];
    const float* w_phi  = (const float*)d_in[7];
    const float* b_phi  = (const float*)d_in[8];
    const float* w_ctx  = (const float*)d_in[9];
    const float* w_self = (const float*)d_in[10];
    const float* b_self = (const float*)d_in[11];
    const float* w_out  = (const float*)d_in[12];
    const float* b_out  = (const float*)d_in[13];
    float* out = (float*)d_out;

    k_projx<<<dim3(22, 16), 256>>>(x, w_attn, b_attn, w_node, b_node,
                                   batch, q, w_phi, b_phi, w_ctx,
                                   out + OFF_XHAT, out + OFF_MASK);
    k_zmain<<<dim3(8, NE, BATCHES), 128>>>(w_self, b_self, w_out, b_out,
                                           out + OFF_EHAT, out + OFF_EDGE);
}